// round 3
// baseline (speedup 1.0000x reference)
#include <cuda_runtime.h>

#define N_NODES 50000
#define N_EDGES 800000
#define D 128

// ---------------- device scratch (no runtime allocation allowed) ----------
__device__ int   g_deg[N_NODES];
__device__ int   g_rowptr[N_NODES + 1];
__device__ int   g_fill[N_NODES];
__device__ int   g_col[N_EDGES];
__device__ float g_agg[N_NODES * D];
__device__ float g_h1[N_NODES * D];
__device__ float g_h2[N_NODES * D];
__device__ int   g_not64;   // nonzero -> edge_index is int32

// ---------------- edge dtype detection ------------------------------------
// If edge_index is int64 (values < 2^32), every odd int32 word is 0.
// If int32, odd words are random node ids — virtually never all zero.
__global__ void detect_dtype_kernel(const int* __restrict__ ei32, int E) {
    if (blockIdx.x == 0 && threadIdx.x == 0) g_not64 = 0;
    __syncthreads();
    int i = threadIdx.x;               // sample first 256 pairs
    if (i < 256) {
        if (ei32[2 * i + 1] != 0) atomicOr(&g_not64, 1);
    }
}

// ---------------- CSR build ------------------------------------------------
__global__ void zero_deg_kernel(int n) {
    int i = blockIdx.x * blockDim.x + threadIdx.x;
    if (i < n) g_deg[i] = 0;
}

__global__ void hist_kernel(const void* __restrict__ eiv, int E) {
    int e = blockIdx.x * blockDim.x + threadIdx.x;
    if (e >= E) return;
    int d;
    if (g_not64) d = ((const int*)eiv)[E + e];
    else         d = (int)((const long long*)eiv)[E + e];
    atomicAdd(&g_deg[d], 1);
}

// single-block exclusive scan of g_deg -> g_rowptr (and g_fill copy)
__global__ void scan_kernel(int n) {
    __shared__ int warp_sums[32];
    __shared__ int s_carry;
    const int t = threadIdx.x;
    const int lane = t & 31;
    const int wid = t >> 5;
    if (t == 0) s_carry = 0;
    __syncthreads();

    for (int base = 0; base < n; base += 1024) {
        int i = base + t;
        int v = (i < n) ? g_deg[i] : 0;
        int incl = v;
#pragma unroll
        for (int off = 1; off < 32; off <<= 1) {
            int u = __shfl_up_sync(0xffffffffu, incl, off);
            if (lane >= off) incl += u;
        }
        if (lane == 31) warp_sums[wid] = incl;
        __syncthreads();
        int carry = s_carry;
        if (wid == 0) {
            int ws = warp_sums[lane];
            int wincl = ws;
#pragma unroll
            for (int off = 1; off < 32; off <<= 1) {
                int u = __shfl_up_sync(0xffffffffu, wincl, off);
                if (lane >= off) wincl += u;
            }
            warp_sums[lane] = wincl - ws;
        }
        __syncthreads();
        int excl = carry + warp_sums[wid] + (incl - v);
        if (i < n) {
            g_rowptr[i] = excl;
            g_fill[i]   = excl;
        }
        if (t == 1023) s_carry = excl + v;
        __syncthreads();
    }
    if (t == 0) g_rowptr[n] = s_carry;
}

__global__ void scatter_kernel(const void* __restrict__ eiv, int E) {
    int e = blockIdx.x * blockDim.x + threadIdx.x;
    if (e >= E) return;
    int s, d;
    if (g_not64) {
        s = ((const int*)eiv)[e];
        d = ((const int*)eiv)[E + e];
    } else {
        s = (int)((const long long*)eiv)[e];
        d = (int)((const long long*)eiv)[E + e];
    }
    int pos = atomicAdd(&g_fill[d], 1);
    g_col[pos] = s;
}

// ---------------- mean aggregation: one warp per dst node -----------------
__global__ void aggregate_kernel(const float4* __restrict__ x, int n, int use_h1) {
    int warp = (blockIdx.x * blockDim.x + threadIdx.x) >> 5;
    int lane = threadIdx.x & 31;
    if (warp >= n) return;
    const float4* __restrict__ src = use_h1 ? (const float4*)g_h1 : x;
    int beg = g_rowptr[warp];
    int end = g_rowptr[warp + 1];
    float4 acc = make_float4(0.f, 0.f, 0.f, 0.f);
    for (int e = beg; e < end; ++e) {
        int s = g_col[e];
        float4 v = src[(long)s * 32 + lane];
        acc.x += v.x; acc.y += v.y; acc.z += v.z; acc.w += v.w;
    }
    int deg = end - beg;
    float sc = 1.0f / (float)(deg > 0 ? deg : 1);
    acc.x *= sc; acc.y *= sc; acc.z *= sc; acc.w *= sc;
    ((float4*)g_agg)[(long)warp * 32 + lane] = acc;
}

// ---------------- fused SAGE linear: out = relu(agg@Wl + bl + B@Wr) -------
#define KT 16
__global__ void __launch_bounds__(256)
sage_gemm_kernel(const float* __restrict__ Bx,
                 const float* __restrict__ Wl, const float* __restrict__ bl,
                 const float* __restrict__ Wr,
                 int n, int in_sel, int out_sel) {
    __shared__ float sWl[KT][128];
    __shared__ float sWr[KT][128];
    __shared__ float sA[128][KT];
    __shared__ float sB[128][KT];

    const int tid = threadIdx.x;
    const int row0 = blockIdx.x * 128;

    const float* __restrict__ A  = g_agg;
    const float* __restrict__ B  = in_sel ? (const float*)g_h1 : Bx;
    float* __restrict__ out      = (out_sel == 1) ? (float*)g_h1 : (float*)g_h2;

    const int tx = tid & 15;
    const int ty = tid >> 4;
    const int tc = tx * 8;
    const int tr = ty * 8;

    float acc[8][8];
#pragma unroll
    for (int i = 0; i < 8; i++)
#pragma unroll
        for (int j = 0; j < 8; j++) acc[i][j] = 0.f;

    const float4* A4 = (const float4*)A;
    const float4* B4 = (const float4*)B;
    const float4 zero4 = make_float4(0.f, 0.f, 0.f, 0.f);

    for (int kt = 0; kt < 128 / KT; kt++) {
        __syncthreads();
#pragma unroll
        for (int u = 0; u < 2; u++) {
            int idx = tid + u * 256;
            int kk = idx >> 5;
            int c4 = idx & 31;
            ((float4*)&sWl[kk][0])[c4] = ((const float4*)&Wl[(kt * KT + kk) * 128])[c4];
            ((float4*)&sWr[kk][0])[c4] = ((const float4*)&Wr[(kt * KT + kk) * 128])[c4];
        }
#pragma unroll
        for (int u = 0; u < 2; u++) {
            int idx = tid + u * 256;
            int r  = idx >> 2;
            int c4 = idx & 3;
            int gr = row0 + r;
            float4 va = zero4, vb = zero4;
            if (gr < n) {
                va = A4[(long)gr * 32 + kt * 4 + c4];
                vb = B4[(long)gr * 32 + kt * 4 + c4];
            }
            ((float4*)&sA[r][0])[c4] = va;
            ((float4*)&sB[r][0])[c4] = vb;
        }
        __syncthreads();

#pragma unroll
        for (int kk = 0; kk < KT; kk++) {
            float4 wl0 = ((const float4*)&sWl[kk][0])[tx * 2];
            float4 wl1 = ((const float4*)&sWl[kk][0])[tx * 2 + 1];
            float4 wr0 = ((const float4*)&sWr[kk][0])[tx * 2];
            float4 wr1 = ((const float4*)&sWr[kk][0])[tx * 2 + 1];
            float wlv[8] = {wl0.x, wl0.y, wl0.z, wl0.w, wl1.x, wl1.y, wl1.z, wl1.w};
            float wrv[8] = {wr0.x, wr0.y, wr0.z, wr0.w, wr1.x, wr1.y, wr1.z, wr1.w};
#pragma unroll
            for (int i = 0; i < 8; i++) {
                float a = sA[tr + i][kk];
                float b = sB[tr + i][kk];
#pragma unroll
                for (int j = 0; j < 8; j++) {
                    acc[i][j] = fmaf(a, wlv[j], acc[i][j]);
                    acc[i][j] = fmaf(b, wrv[j], acc[i][j]);
                }
            }
        }
    }

    float bias[8];
#pragma unroll
    for (int j = 0; j < 8; j++) bias[j] = bl[tc + j];

#pragma unroll
    for (int i = 0; i < 8; i++) {
        int gr = row0 + tr + i;
        if (gr >= n) continue;
        float v[8];
#pragma unroll
        for (int j = 0; j < 8; j++) {
            float t = acc[i][j] + bias[j];
            v[j] = t > 0.f ? t : 0.f;
        }
        float4* o = (float4*)&out[(long)gr * 128 + tc];
        o[0] = make_float4(v[0], v[1], v[2], v[3]);
        o[1] = make_float4(v[4], v[5], v[6], v[7]);
    }
}

// ---------------- output head: out[i] = g_h2[i] . Wout + bout -------------
__global__ void head_kernel(const float* __restrict__ Wout,
                            const float* __restrict__ bout,
                            float* __restrict__ out, int n) {
    int warp = (blockIdx.x * blockDim.x + threadIdx.x) >> 5;
    int lane = threadIdx.x & 31;
    if (warp >= n) return;
    float4 hv = ((const float4*)g_h2)[(long)warp * 32 + lane];
    float4 wv = ((const float4*)Wout)[lane];
    float d = hv.x * wv.x + hv.y * wv.y + hv.z * wv.z + hv.w * wv.w;
#pragma unroll
    for (int off = 16; off > 0; off >>= 1)
        d += __shfl_xor_sync(0xffffffffu, d, off);
    if (lane == 0) out[warp] = d + bout[0];
}

// ---------------- launch ---------------------------------------------------
extern "C" void kernel_launch(void* const* d_in, const int* in_sizes, int n_in,
                              void* d_out, int out_size) {
    const float* x    = (const float*)d_in[0];
    const void*  ei   = d_in[1];
    const float* W1l  = (const float*)d_in[2];
    const float* b1l  = (const float*)d_in[3];
    const float* W1r  = (const float*)d_in[4];
    const float* W2l  = (const float*)d_in[5];
    const float* b2l  = (const float*)d_in[6];
    const float* W2r  = (const float*)d_in[7];
    const float* Wout = (const float*)d_in[8];
    const float* bout = (const float*)d_in[9];
    float*       out  = (float*)d_out;

    const int n = in_sizes[0] / D;    // 50000
    const int E = in_sizes[1] / 2;    // 800000

    // --- dtype probe + CSR build ---
    detect_dtype_kernel<<<1, 256>>>((const int*)ei, E);
    zero_deg_kernel<<<(n + 255) / 256, 256>>>(n);
    hist_kernel<<<(E + 255) / 256, 256>>>(ei, E);
    scan_kernel<<<1, 1024>>>(n);
    scatter_kernel<<<(E + 255) / 256, 256>>>(ei, E);

    const int aggBlocks  = (n * 32 + 255) / 256;
    const int gemmBlocks = (n + 127) / 128;

    // --- layer 1 ---
    aggregate_kernel<<<aggBlocks, 256>>>((const float4*)x, n, 0);
    sage_gemm_kernel<<<gemmBlocks, 256>>>(x, W1l, b1l, W1r, n, 0, 1);

    // --- layer 2 ---
    aggregate_kernel<<<aggBlocks, 256>>>((const float4*)x, n, 1);
    sage_gemm_kernel<<<gemmBlocks, 256>>>(x, W2l, b2l, W2r, n, 1, 2);

    // --- head ---
    head_kernel<<<(n * 32 + 255) / 256, 256>>>(Wout, bout, out, n);
}

// round 4
// speedup vs baseline: 1.0726x; 1.0726x over previous
#include <cuda_runtime.h>

#define N_NODES 50000
#define N_EDGES 800000
#define D 128

// ---------------- device scratch (no runtime allocation allowed) ----------
__device__ int   g_deg[N_NODES];
__device__ int   g_rowptr[N_NODES + 1];
__device__ int   g_fill[N_NODES];
__device__ int   g_col[N_EDGES];
__device__ float g_agg[N_NODES * D];
__device__ float g_h1[N_NODES * D];
__device__ float g_h2[N_NODES * D];
__device__ int   g_not64;   // nonzero -> edge_index is int32
__device__ int   g_bsum[64];
__device__ int   g_boff[64];

// ---------------- f32x2 packed math helpers (sm_100+) ---------------------
__device__ __forceinline__ unsigned long long pack2(float lo, float hi) {
    unsigned long long r;
    asm("mov.b64 %0, {%1, %2};" : "=l"(r) : "f"(lo), "f"(hi));
    return r;
}
__device__ __forceinline__ unsigned long long fma2(unsigned long long a,
                                                   unsigned long long b,
                                                   unsigned long long c) {
    unsigned long long d;
    asm("fma.rn.f32x2 %0, %1, %2, %3;" : "=l"(d) : "l"(a), "l"(b), "l"(c));
    return d;
}
__device__ __forceinline__ float2 unpack2(unsigned long long v) {
    float2 f;
    asm("mov.b64 {%0, %1}, %2;" : "=f"(f.x), "=f"(f.y) : "l"(v));
    return f;
}

// ---------------- edge dtype detection ------------------------------------
__global__ void detect_dtype_kernel(const int* __restrict__ ei32, int E) {
    if (threadIdx.x == 0) g_not64 = 0;
    __syncthreads();
    int i = threadIdx.x;
    if (i < 256) {
        if (ei32[2 * i + 1] != 0) atomicOr(&g_not64, 1);
    }
}

// ---------------- CSR build ------------------------------------------------
__global__ void zero_deg_kernel(int n) {
    int i = blockIdx.x * blockDim.x + threadIdx.x;
    if (i < n) g_deg[i] = 0;
}

__global__ void hist_kernel(const void* __restrict__ eiv, int E) {
    int e = blockIdx.x * blockDim.x + threadIdx.x;
    if (e >= E) return;
    int d;
    if (g_not64) d = ((const int*)eiv)[E + e];
    else         d = (int)((const long long*)eiv)[E + e];
    atomicAdd(&g_deg[d], 1);
}

// ---- hierarchical scan: phase 1 — per-block (1024 elems) sums ------------
__global__ void scan_blocksum_kernel(int n) {
    int base = blockIdx.x * 1024;
    int t = threadIdx.x;
    int v = 0;
#pragma unroll
    for (int u = 0; u < 4; u++) {
        int i = base + t + u * 256;
        if (i < n) v += g_deg[i];
    }
#pragma unroll
    for (int off = 16; off; off >>= 1) v += __shfl_xor_sync(0xffffffffu, v, off);
    __shared__ int ws[8];
    if ((t & 31) == 0) ws[t >> 5] = v;
    __syncthreads();
    if (t < 8) {
        int s = ws[t];
#pragma unroll
        for (int off = 4; off; off >>= 1) s += __shfl_xor_sync(0xffu, s, off);
        if (t == 0) g_bsum[blockIdx.x] = s;
    }
}

// ---- phase 2 — scan the (<=64) block sums; also writes rowptr[n] ---------
__global__ void scan_offsets_kernel(int nb, int n) {
    __shared__ int w0sum;
    int t = threadIdx.x;                 // 0..63
    int lane = t & 31;
    int v = (t < nb) ? g_bsum[t] : 0;
    int incl = v;
#pragma unroll
    for (int off = 1; off < 32; off <<= 1) {
        int u = __shfl_up_sync(0xffffffffu, incl, off);
        if (lane >= off) incl += u;
    }
    if (t == 31) w0sum = incl;
    __syncthreads();
    if (t >= 32) incl += w0sum;
    if (t < nb) g_boff[t] = incl - v;
    if (t == nb - 1) g_rowptr[n] = incl;
}

// ---- phase 3 — per-block exclusive scan with offset -----------------------
__global__ void scan_final_kernel(int n) {
    int t = threadIdx.x;
    int i0 = blockIdx.x * 1024 + t * 4;
    int vals[4];
    int local = 0;
#pragma unroll
    for (int u = 0; u < 4; u++) {
        int i = i0 + u;
        vals[u] = (i < n) ? g_deg[i] : 0;
        local += vals[u];
    }
    int lane = t & 31, wid = t >> 5;
    int incl = local;
#pragma unroll
    for (int off = 1; off < 32; off <<= 1) {
        int u = __shfl_up_sync(0xffffffffu, incl, off);
        if (lane >= off) incl += u;
    }
    __shared__ int ws[8];
    __shared__ int wexcl[8];
    if (lane == 31) ws[wid] = incl;
    __syncthreads();
    if (t < 8) {
        int s = ws[t];
        int si = s;
#pragma unroll
        for (int off = 1; off < 8; off <<= 1) {
            int u = __shfl_up_sync(0xffu, si, off);
            if (t >= off) si += u;
        }
        wexcl[t] = si - s;
    }
    __syncthreads();
    int excl = g_boff[blockIdx.x] + wexcl[wid] + (incl - local);
#pragma unroll
    for (int u = 0; u < 4; u++) {
        int i = i0 + u;
        if (i < n) { g_rowptr[i] = excl; g_fill[i] = excl; }
        excl += vals[u];
    }
}

__global__ void scatter_kernel(const void* __restrict__ eiv, int E) {
    int e = blockIdx.x * blockDim.x + threadIdx.x;
    if (e >= E) return;
    int s, d;
    if (g_not64) {
        s = ((const int*)eiv)[e];
        d = ((const int*)eiv)[E + e];
    } else {
        s = (int)((const long long*)eiv)[e];
        d = (int)((const long long*)eiv)[E + e];
    }
    int pos = atomicAdd(&g_fill[d], 1);
    g_col[pos] = s;
}

// ---------------- mean aggregation: one warp per dst node -----------------
__global__ void aggregate_kernel(const float4* __restrict__ x, int n, int use_h1) {
    int warp = (blockIdx.x * blockDim.x + threadIdx.x) >> 5;
    int lane = threadIdx.x & 31;
    if (warp >= n) return;
    const float4* __restrict__ src = use_h1 ? (const float4*)g_h1 : x;
    int beg = g_rowptr[warp];
    int end = g_rowptr[warp + 1];
    float4 acc = make_float4(0.f, 0.f, 0.f, 0.f);
    for (int e = beg; e < end; ++e) {
        int s = g_col[e];
        float4 v = src[(long)s * 32 + lane];
        acc.x += v.x; acc.y += v.y; acc.z += v.z; acc.w += v.w;
    }
    int deg = end - beg;
    float sc = 1.0f / (float)(deg > 0 ? deg : 1);
    acc.x *= sc; acc.y *= sc; acc.z *= sc; acc.w *= sc;
    ((float4*)g_agg)[(long)warp * 32 + lane] = acc;
}

// ---------------- fused SAGE linear: out = relu(agg@Wl + bl + B@Wr) -------
// f32x2 packed-FFMA version. A/B tiles stored k-major (transposed).
#define KT 16
__global__ void __launch_bounds__(256)
sage_gemm_kernel(const float* __restrict__ Bx,
                 const float* __restrict__ Wl, const float* __restrict__ bl,
                 const float* __restrict__ Wr,
                 int n, int in_sel, int out_sel) {
    __shared__ __align__(16) float sWl[KT][128];
    __shared__ __align__(16) float sWr[KT][128];
    __shared__ __align__(16) float sAT[KT][128];   // [k][row]
    __shared__ __align__(16) float sBT[KT][128];

    const int tid = threadIdx.x;
    const int row0 = blockIdx.x * 128;

    const float* __restrict__ A  = g_agg;
    const float* __restrict__ B  = in_sel ? (const float*)g_h1 : Bx;
    float* __restrict__ out      = (out_sel == 1) ? (float*)g_h1 : (float*)g_h2;

    const int tx = tid & 15;          // column group: 8 cols = 4 f32x2 pairs
    const int ty = tid >> 4;          // row group: 8 rows
    const int tc = tx * 8;
    const int tr = ty * 8;

    unsigned long long accl[8][4];
    unsigned long long accr[8][4];
#pragma unroll
    for (int i = 0; i < 8; i++)
#pragma unroll
        for (int j = 0; j < 4; j++) { accl[i][j] = 0ull; accr[i][j] = 0ull; }

    const float4* A4 = (const float4*)A;
    const float4* B4 = (const float4*)B;
    const float4 zero4 = make_float4(0.f, 0.f, 0.f, 0.f);

    for (int kt = 0; kt < 128 / KT; kt++) {
        __syncthreads();
        // weights: KT x 128 = 512 float4, 2 per thread
#pragma unroll
        for (int u = 0; u < 2; u++) {
            int idx = tid + u * 256;
            int kk = idx >> 5;
            int c4 = idx & 31;
            ((float4*)&sWl[kk][0])[c4] = ((const float4*)&Wl[(kt * KT + kk) * 128])[c4];
            ((float4*)&sWr[kk][0])[c4] = ((const float4*)&Wr[(kt * KT + kk) * 128])[c4];
        }
        // A/B: 128 rows x KT cols, loaded as float4 (4 k's), stored transposed
#pragma unroll
        for (int u = 0; u < 2; u++) {
            int idx = tid + u * 256;
            int r  = idx >> 2;
            int c4 = idx & 3;
            int gr = row0 + r;
            float4 va = zero4, vb = zero4;
            if (gr < n) {
                va = A4[(long)gr * 32 + kt * 4 + c4];
                vb = B4[(long)gr * 32 + kt * 4 + c4];
            }
            int kb = c4 * 4;
            sAT[kb + 0][r] = va.x; sAT[kb + 1][r] = va.y;
            sAT[kb + 2][r] = va.z; sAT[kb + 3][r] = va.w;
            sBT[kb + 0][r] = vb.x; sBT[kb + 1][r] = vb.y;
            sBT[kb + 2][r] = vb.z; sBT[kb + 3][r] = vb.w;
        }
        __syncthreads();

#pragma unroll
        for (int kk = 0; kk < KT; kk++) {
            ulonglong2 l0 = *(const ulonglong2*)&sWl[kk][tc];
            ulonglong2 l1 = *(const ulonglong2*)&sWl[kk][tc + 4];
            ulonglong2 r0 = *(const ulonglong2*)&sWr[kk][tc];
            ulonglong2 r1 = *(const ulonglong2*)&sWr[kk][tc + 4];
            unsigned long long wlv[4] = {l0.x, l0.y, l1.x, l1.y};
            unsigned long long wrv[4] = {r0.x, r0.y, r1.x, r1.y};
            float4 a0 = *(const float4*)&sAT[kk][tr];
            float4 a1 = *(const float4*)&sAT[kk][tr + 4];
            float4 b0 = *(const float4*)&sBT[kk][tr];
            float4 b1 = *(const float4*)&sBT[kk][tr + 4];
            float av[8] = {a0.x, a0.y, a0.z, a0.w, a1.x, a1.y, a1.z, a1.w};
            float bv[8] = {b0.x, b0.y, b0.z, b0.w, b1.x, b1.y, b1.z, b1.w};
#pragma unroll
            for (int i = 0; i < 8; i++) {
                unsigned long long a2 = pack2(av[i], av[i]);
                unsigned long long b2 = pack2(bv[i], bv[i]);
#pragma unroll
                for (int j = 0; j < 4; j++) {
                    accl[i][j] = fma2(a2, wlv[j], accl[i][j]);
                    accr[i][j] = fma2(b2, wrv[j], accr[i][j]);
                }
            }
        }
    }

    float bias[8];
#pragma unroll
    for (int j = 0; j < 8; j++) bias[j] = bl[tc + j];

#pragma unroll
    for (int i = 0; i < 8; i++) {
        int gr = row0 + tr + i;
        if (gr >= n) continue;
        float v[8];
#pragma unroll
        for (int j = 0; j < 4; j++) {
            float2 pl = unpack2(accl[i][j]);
            float2 pr = unpack2(accr[i][j]);
            v[2 * j]     = pl.x + pr.x + bias[2 * j];
            v[2 * j + 1] = pl.y + pr.y + bias[2 * j + 1];
        }
#pragma unroll
        for (int j = 0; j < 8; j++) v[j] = v[j] > 0.f ? v[j] : 0.f;
        float4* o = (float4*)&out[(long)gr * 128 + tc];
        o[0] = make_float4(v[0], v[1], v[2], v[3]);
        o[1] = make_float4(v[4], v[5], v[6], v[7]);
    }
}

// ---------------- output head: out[i] = g_h2[i] . Wout + bout -------------
__global__ void head_kernel(const float* __restrict__ Wout,
                            const float* __restrict__ bout,
                            float* __restrict__ out, int n) {
    int warp = (blockIdx.x * blockDim.x + threadIdx.x) >> 5;
    int lane = threadIdx.x & 31;
    if (warp >= n) return;
    float4 hv = ((const float4*)g_h2)[(long)warp * 32 + lane];
    float4 wv = ((const float4*)Wout)[lane];
    float d = hv.x * wv.x + hv.y * wv.y + hv.z * wv.z + hv.w * wv.w;
#pragma unroll
    for (int off = 16; off > 0; off >>= 1)
        d += __shfl_xor_sync(0xffffffffu, d, off);
    if (lane == 0) out[warp] = d + bout[0];
}

// ---------------- launch ---------------------------------------------------
extern "C" void kernel_launch(void* const* d_in, const int* in_sizes, int n_in,
                              void* d_out, int out_size) {
    const float* x    = (const float*)d_in[0];
    const void*  ei   = d_in[1];
    const float* W1l  = (const float*)d_in[2];
    const float* b1l  = (const float*)d_in[3];
    const float* W1r  = (const float*)d_in[4];
    const float* W2l  = (const float*)d_in[5];
    const float* b2l  = (const float*)d_in[6];
    const float* W2r  = (const float*)d_in[7];
    const float* Wout = (const float*)d_in[8];
    const float* bout = (const float*)d_in[9];
    float*       out  = (float*)d_out;

    const int n = in_sizes[0] / D;    // 50000
    const int E = in_sizes[1] / 2;    // 800000
    const int nb = (n + 1023) / 1024; // scan blocks (<= 64)

    // --- dtype probe + CSR build ---
    detect_dtype_kernel<<<1, 256>>>((const int*)ei, E);
    zero_deg_kernel<<<(n + 255) / 256, 256>>>(n);
    hist_kernel<<<(E + 255) / 256, 256>>>(ei, E);
    scan_blocksum_kernel<<<nb, 256>>>(n);
    scan_offsets_kernel<<<1, 64>>>(nb, n);
    scan_final_kernel<<<nb, 256>>>(n);
    scatter_kernel<<<(E + 255) / 256, 256>>>(ei, E);

    const int aggBlocks  = (n * 32 + 255) / 256;
    const int gemmBlocks = (n + 127) / 128;

    // --- layer 1 ---
    aggregate_kernel<<<aggBlocks, 256>>>((const float4*)x, n, 0);
    sage_gemm_kernel<<<gemmBlocks, 256>>>(x, W1l, b1l, W1r, n, 0, 1);

    // --- layer 2 ---
    aggregate_kernel<<<aggBlocks, 256>>>((const float4*)x, n, 1);
    sage_gemm_kernel<<<gemmBlocks, 256>>>(x, W2l, b2l, W2r, n, 1, 2);

    // --- head ---
    head_kernel<<<(n * 32 + 255) / 256, 256>>>(Wout, bout, out, n);
}

// round 5
// speedup vs baseline: 1.1213x; 1.0454x over previous
#include <cuda_runtime.h>

#define N_NODES 50000
#define N_EDGES 800000
#define D 128

// ---------------- device scratch (no runtime allocation allowed) ----------
__device__ int   g_deg[N_NODES];
__device__ int   g_rowptr[N_NODES + 1];
__device__ int   g_fill[N_NODES];
__device__ int   g_col[N_EDGES];
__device__ float g_agg[N_NODES * D];
__device__ float g_h1[N_NODES * D];
__device__ float g_h2[N_NODES * D];
__device__ int   g_not64;        // nonzero -> edge_index is int32
__device__ int   g_blk_agg[64];
__device__ int   g_blk_incl[64];
__device__ int   g_blk_flag[64]; // 0=empty 1=partial 2=complete

// ---------------- f32x2 packed math helpers (sm_100+) ---------------------
__device__ __forceinline__ unsigned long long pack2(float lo, float hi) {
    unsigned long long r;
    asm("mov.b64 %0, {%1, %2};" : "=l"(r) : "f"(lo), "f"(hi));
    return r;
}
__device__ __forceinline__ unsigned long long fma2(unsigned long long a,
                                                   unsigned long long b,
                                                   unsigned long long c) {
    unsigned long long d;
    asm("fma.rn.f32x2 %0, %1, %2, %3;" : "=l"(d) : "l"(a), "l"(b), "l"(c));
    return d;
}
__device__ __forceinline__ float2 unpack2(unsigned long long v) {
    float2 f;
    asm("mov.b64 {%0, %1}, %2;" : "=f"(f.x), "=f"(f.y) : "l"(v));
    return f;
}

// ---------------- zero + dtype probe (one launch) --------------------------
// If edge_index is int64 (values < 2^32), every odd int32 word is 0.
__global__ void zero_kernel(const int* __restrict__ ei32, int n) {
    int i = blockIdx.x * blockDim.x + threadIdx.x;
    if (i < n) g_deg[i] = 0;
    if (i < 64) { g_blk_flag[i] = 0; }
    if (blockIdx.x == 0) {
        if (threadIdx.x == 0) g_not64 = 0;
        __syncthreads();
        if (threadIdx.x < 256 && ei32[2 * threadIdx.x + 1] != 0)
            atomicOr(&g_not64, 1);
    }
}

__global__ void hist_kernel(const void* __restrict__ eiv, int E) {
    int e = blockIdx.x * blockDim.x + threadIdx.x;
    if (e >= E) return;
    int d;
    if (g_not64) d = ((const int*)eiv)[E + e];
    else         d = (int)((const long long*)eiv)[E + e];
    atomicAdd(&g_deg[d], 1);
}

// ---- single-pass decoupled-lookback exclusive scan ------------------------
__global__ void scan_lookback_kernel(int n, int nb) {
    const int b = blockIdx.x;
    const int t = threadIdx.x;
    const int lane = t & 31, wid = t >> 5;
    int i0 = b * 1024 + t * 4;

    int vals[4]; int local = 0;
#pragma unroll
    for (int u = 0; u < 4; u++) {
        int i = i0 + u;
        vals[u] = (i < n) ? g_deg[i] : 0;
        local += vals[u];
    }
    int incl = local;
#pragma unroll
    for (int off = 1; off < 32; off <<= 1) {
        int u = __shfl_up_sync(0xffffffffu, incl, off);
        if (lane >= off) incl += u;
    }
    __shared__ int ws[8], wexcl[8];
    __shared__ int s_prefix;
    if (lane == 31) ws[wid] = incl;
    __syncthreads();
    if (t < 8) {
        int s = ws[t];
        int si = s;
#pragma unroll
        for (int off = 1; off < 8; off <<= 1) {
            int u = __shfl_up_sync(0xffu, si, off);
            if (t >= off) si += u;
        }
        wexcl[t] = si - s;
    }
    __syncthreads();
    const int total = wexcl[7] + ws[7];

    // publish partial aggregate
    if (t == 0) {
        g_blk_agg[b] = total;
        __threadfence();
        ((volatile int*)g_blk_flag)[b] = 1;
    }

    // warp 0: parallel lookback
    if (wid == 0) {
        int prefix = 0;
        int j = b - 1;
        while (j >= 0) {
            int jj = j - lane;
            int f = 0, v = 0;
            if (jj >= 0) {
                do { f = ((volatile int*)g_blk_flag)[jj]; } while (f == 0);
                __threadfence();
                v = (f == 2) ? ((volatile int*)g_blk_incl)[jj]
                             : ((volatile int*)g_blk_agg)[jj];
            }
            unsigned done = __ballot_sync(0xffffffffu, jj >= 0 && f == 2);
            if (done) {
                int fl = __ffs(done) - 1;     // nearest complete block
                int contrib = (lane <= fl) ? v : 0;
#pragma unroll
                for (int off = 16; off; off >>= 1)
                    contrib += __shfl_xor_sync(0xffffffffu, contrib, off);
                prefix += contrib;
                break;
            } else {
                int contrib = (jj >= 0) ? v : 0;
#pragma unroll
                for (int off = 16; off; off >>= 1)
                    contrib += __shfl_xor_sync(0xffffffffu, contrib, off);
                prefix += contrib;
                j -= 32;
            }
        }
        if (lane == 0) {
            g_blk_incl[b] = prefix + total;
            __threadfence();
            ((volatile int*)g_blk_flag)[b] = 2;
            s_prefix = prefix;
            if (b == nb - 1) g_rowptr[n] = prefix + total;
        }
    }
    __syncthreads();

    int excl = s_prefix + wexcl[wid] + (incl - local);
#pragma unroll
    for (int u = 0; u < 4; u++) {
        int i = i0 + u;
        if (i < n) { g_rowptr[i] = excl; g_fill[i] = excl; }
        excl += vals[u];
    }
}

__global__ void scatter_kernel(const void* __restrict__ eiv, int E) {
    int e = blockIdx.x * blockDim.x + threadIdx.x;
    if (e >= E) return;
    int s, d;
    if (g_not64) {
        s = ((const int*)eiv)[e];
        d = ((const int*)eiv)[E + e];
    } else {
        s = (int)((const long long*)eiv)[e];
        d = (int)((const long long*)eiv)[E + e];
    }
    int pos = atomicAdd(&g_fill[d], 1);
    g_col[pos] = s;
}

// ---------------- mean aggregation: one warp per dst node -----------------
__global__ void aggregate_kernel(const float4* __restrict__ x, int n, int use_h1) {
    int warp = (blockIdx.x * blockDim.x + threadIdx.x) >> 5;
    int lane = threadIdx.x & 31;
    if (warp >= n) return;
    const float4* __restrict__ src = use_h1 ? (const float4*)g_h1 : x;
    int beg = g_rowptr[warp];
    int end = g_rowptr[warp + 1];
    float4 acc = make_float4(0.f, 0.f, 0.f, 0.f);
    for (int e = beg; e < end; ++e) {
        int s = g_col[e];
        float4 v = src[(long)s * 32 + lane];
        acc.x += v.x; acc.y += v.y; acc.z += v.z; acc.w += v.w;
    }
    int deg = end - beg;
    float sc = 1.0f / (float)(deg > 0 ? deg : 1);
    acc.x *= sc; acc.y *= sc; acc.z *= sc; acc.w *= sc;
    ((float4*)g_agg)[(long)warp * 32 + lane] = acc;
}

// ---------------- fused SAGE linear: out = relu(agg@Wl + bl + B@Wr) -------
// f32x2 packed FFMA, SINGLE merged accumulator bank, software-pipelined loads.
#define KT 16
__global__ void __launch_bounds__(256)
sage_gemm_kernel(const float* __restrict__ Bx,
                 const float* __restrict__ Wl, const float* __restrict__ bl,
                 const float* __restrict__ Wr,
                 int n, int in_sel, int out_sel) {
    __shared__ __align__(16) float sWl[KT][128];
    __shared__ __align__(16) float sWr[KT][128];
    __shared__ __align__(16) float sAT[KT][128];   // [k][row]
    __shared__ __align__(16) float sBT[KT][128];

    const int tid = threadIdx.x;
    const int row0 = blockIdx.x * 128;

    const float* __restrict__ A  = g_agg;
    const float* __restrict__ B  = in_sel ? (const float*)g_h1 : Bx;
    float* __restrict__ out      = (out_sel == 1) ? (float*)g_h1 : (float*)g_h2;

    const int tx = tid & 15;
    const int ty = tid >> 4;
    const int tc = tx * 8;
    const int tr = ty * 8;

    unsigned long long acc[8][4];
#pragma unroll
    for (int i = 0; i < 8; i++)
#pragma unroll
        for (int j = 0; j < 4; j++) acc[i][j] = 0ull;

    const float4* A4 = (const float4*)A;
    const float4* B4 = (const float4*)B;
    const float4 zero4 = make_float4(0.f, 0.f, 0.f, 0.f);

    // per-thread load slots (2 per array per tile)
    const int widx0 = tid,        widx1 = tid + 256;   // weight float4 ids
    const int wk0 = widx0 >> 5,   wc0 = widx0 & 31;
    const int wk1 = widx1 >> 5,   wc1 = widx1 & 31;
    const int r0_ = widx0 >> 2,   c40 = widx0 & 3;     // A/B slots
    const int r1_ = widx1 >> 2,   c41 = widx1 & 3;

    float4 pWl0, pWl1, pWr0, pWr1, pA0, pA1, pB0, pB1;

    // preload tile 0
    {
        pWl0 = ((const float4*)&Wl[wk0 * 128])[wc0];
        pWl1 = ((const float4*)&Wl[wk1 * 128])[wc1];
        pWr0 = ((const float4*)&Wr[wk0 * 128])[wc0];
        pWr1 = ((const float4*)&Wr[wk1 * 128])[wc1];
        int ga = row0 + r0_, gb = row0 + r1_;
        pA0 = (ga < n) ? A4[(long)ga * 32 + c40] : zero4;
        pB0 = (ga < n) ? B4[(long)ga * 32 + c40] : zero4;
        pA1 = (gb < n) ? A4[(long)gb * 32 + c41] : zero4;
        pB1 = (gb < n) ? B4[(long)gb * 32 + c41] : zero4;
    }

    for (int kt = 0; kt < 128 / KT; kt++) {
        __syncthreads();
        // commit preloaded regs to smem
        ((float4*)&sWl[wk0][0])[wc0] = pWl0;
        ((float4*)&sWl[wk1][0])[wc1] = pWl1;
        ((float4*)&sWr[wk0][0])[wc0] = pWr0;
        ((float4*)&sWr[wk1][0])[wc1] = pWr1;
        {
            int kb0 = c40 * 4, kb1 = c41 * 4;
            sAT[kb0 + 0][r0_] = pA0.x; sAT[kb0 + 1][r0_] = pA0.y;
            sAT[kb0 + 2][r0_] = pA0.z; sAT[kb0 + 3][r0_] = pA0.w;
            sBT[kb0 + 0][r0_] = pB0.x; sBT[kb0 + 1][r0_] = pB0.y;
            sBT[kb0 + 2][r0_] = pB0.z; sBT[kb0 + 3][r0_] = pB0.w;
            sAT[kb1 + 0][r1_] = pA1.x; sAT[kb1 + 1][r1_] = pA1.y;
            sAT[kb1 + 2][r1_] = pA1.z; sAT[kb1 + 3][r1_] = pA1.w;
            sBT[kb1 + 0][r1_] = pB1.x; sBT[kb1 + 1][r1_] = pB1.y;
            sBT[kb1 + 2][r1_] = pB1.z; sBT[kb1 + 3][r1_] = pB1.w;
        }
        __syncthreads();

        // preload next tile while computing this one
        if (kt < 128 / KT - 1) {
            int kofs = (kt + 1) * KT;
            pWl0 = ((const float4*)&Wl[(kofs + wk0) * 128])[wc0];
            pWl1 = ((const float4*)&Wl[(kofs + wk1) * 128])[wc1];
            pWr0 = ((const float4*)&Wr[(kofs + wk0) * 128])[wc0];
            pWr1 = ((const float4*)&Wr[(kofs + wk1) * 128])[wc1];
            int c4base = (kt + 1) * 4;
            int ga = row0 + r0_, gb = row0 + r1_;
            pA0 = (ga < n) ? A4[(long)ga * 32 + c4base + c40] : zero4;
            pB0 = (ga < n) ? B4[(long)ga * 32 + c4base + c40] : zero4;
            pA1 = (gb < n) ? A4[(long)gb * 32 + c4base + c41] : zero4;
            pB1 = (gb < n) ? B4[(long)gb * 32 + c4base + c41] : zero4;
        }

#pragma unroll
        for (int kk = 0; kk < KT; kk++) {
            ulonglong2 l0 = *(const ulonglong2*)&sWl[kk][tc];
            ulonglong2 l1 = *(const ulonglong2*)&sWl[kk][tc + 4];
            ulonglong2 r0 = *(const ulonglong2*)&sWr[kk][tc];
            ulonglong2 r1 = *(const ulonglong2*)&sWr[kk][tc + 4];
            unsigned long long wlv[4] = {l0.x, l0.y, l1.x, l1.y};
            unsigned long long wrv[4] = {r0.x, r0.y, r1.x, r1.y};
            float4 a0 = *(const float4*)&sAT[kk][tr];
            float4 a1 = *(const float4*)&sAT[kk][tr + 4];
            float4 b0 = *(const float4*)&sBT[kk][tr];
            float4 b1 = *(const float4*)&sBT[kk][tr + 4];
            float av[8] = {a0.x, a0.y, a0.z, a0.w, a1.x, a1.y, a1.z, a1.w};
            float bv[8] = {b0.x, b0.y, b0.z, b0.w, b1.x, b1.y, b1.z, b1.w};
#pragma unroll
            for (int i = 0; i < 8; i++) {
                unsigned long long a2 = pack2(av[i], av[i]);
                unsigned long long b2 = pack2(bv[i], bv[i]);
#pragma unroll
                for (int j = 0; j < 4; j++) {
                    acc[i][j] = fma2(a2, wlv[j], acc[i][j]);
                    acc[i][j] = fma2(b2, wrv[j], acc[i][j]);
                }
            }
        }
    }

    float bias[8];
#pragma unroll
    for (int j = 0; j < 8; j++) bias[j] = bl[tc + j];

#pragma unroll
    for (int i = 0; i < 8; i++) {
        int gr = row0 + tr + i;
        if (gr >= n) continue;
        float v[8];
#pragma unroll
        for (int j = 0; j < 4; j++) {
            float2 p = unpack2(acc[i][j]);
            v[2 * j]     = p.x + bias[2 * j];
            v[2 * j + 1] = p.y + bias[2 * j + 1];
        }
#pragma unroll
        for (int j = 0; j < 8; j++) v[j] = v[j] > 0.f ? v[j] : 0.f;
        float4* o = (float4*)&out[(long)gr * 128 + tc];
        o[0] = make_float4(v[0], v[1], v[2], v[3]);
        o[1] = make_float4(v[4], v[5], v[6], v[7]);
    }
}

// ---------------- output head: out[i] = g_h2[i] . Wout + bout -------------
__global__ void head_kernel(const float* __restrict__ Wout,
                            const float* __restrict__ bout,
                            float* __restrict__ out, int n) {
    int warp = (blockIdx.x * blockDim.x + threadIdx.x) >> 5;
    int lane = threadIdx.x & 31;
    if (warp >= n) return;
    float4 hv = ((const float4*)g_h2)[(long)warp * 32 + lane];
    float4 wv = ((const float4*)Wout)[lane];
    float d = hv.x * wv.x + hv.y * wv.y + hv.z * wv.z + hv.w * wv.w;
#pragma unroll
    for (int off = 16; off > 0; off >>= 1)
        d += __shfl_xor_sync(0xffffffffu, d, off);
    if (lane == 0) out[warp] = d + bout[0];
}

// ---------------- launch ---------------------------------------------------
extern "C" void kernel_launch(void* const* d_in, const int* in_sizes, int n_in,
                              void* d_out, int out_size) {
    const float* x    = (const float*)d_in[0];
    const void*  ei   = d_in[1];
    const float* W1l  = (const float*)d_in[2];
    const float* b1l  = (const float*)d_in[3];
    const float* W1r  = (const float*)d_in[4];
    const float* W2l  = (const float*)d_in[5];
    const float* b2l  = (const float*)d_in[6];
    const float* W2r  = (const float*)d_in[7];
    const float* Wout = (const float*)d_in[8];
    const float* bout = (const float*)d_in[9];
    float*       out  = (float*)d_out;

    const int n = in_sizes[0] / D;    // 50000
    const int E = in_sizes[1] / 2;    // 800000
    const int nb = (n + 1023) / 1024; // scan blocks (<= 64)

    // --- CSR build (4 launches) ---
    zero_kernel<<<(n + 255) / 256, 256>>>((const int*)ei, n);
    hist_kernel<<<(E + 255) / 256, 256>>>(ei, E);
    scan_lookback_kernel<<<nb, 256>>>(n, nb);
    scatter_kernel<<<(E + 255) / 256, 256>>>(ei, E);

    const int aggBlocks  = (n * 32 + 255) / 256;
    const int gemmBlocks = (n + 127) / 128;

    // --- layer 1 ---  (launch #5 and #6 -> ncu -s 5 captures the GEMM)
    aggregate_kernel<<<aggBlocks, 256>>>((const float4*)x, n, 0);
    sage_gemm_kernel<<<gemmBlocks, 256>>>(x, W1l, b1l, W1r, n, 0, 1);

    // --- layer 2 ---
    aggregate_kernel<<<aggBlocks, 256>>>((const float4*)x, n, 1);
    sage_gemm_kernel<<<gemmBlocks, 256>>>(x, W2l, b2l, W2r, n, 1, 2);

    // --- head ---
    head_kernel<<<(n * 32 + 255) / 256, 256>>>(Wout, bout, out, n);
}

// round 6
// speedup vs baseline: 1.1819x; 1.0540x over previous
#include <cuda_runtime.h>

#define N_NODES 50000
#define N_EDGES 800000
#define D 128
#define KT 16

// ---------------- device scratch (no runtime allocation allowed) ----------
__device__ int   g_deg[N_NODES];
__device__ int   g_rowptr[N_NODES + 1];
__device__ int   g_fill[N_NODES];
__device__ int   g_col[N_EDGES];
__device__ float g_agg[N_NODES * D];
__device__ float g_h1[N_NODES * D];
__device__ float g_h2[N_NODES * D];
__device__ int   g_not64;        // nonzero -> edge_index is int32
__device__ int   g_blk_agg[64];
__device__ int   g_blk_incl[64];
__device__ int   g_blk_flag[64]; // 0=empty 1=partial 2=complete

// ---------------- f32x2 packed math helpers (sm_100+) ---------------------
__device__ __forceinline__ unsigned long long pack2(float lo, float hi) {
    unsigned long long r;
    asm("mov.b64 %0, {%1, %2};" : "=l"(r) : "f"(lo), "f"(hi));
    return r;
}
__device__ __forceinline__ unsigned long long fma2(unsigned long long a,
                                                   unsigned long long b,
                                                   unsigned long long c) {
    unsigned long long d;
    asm("fma.rn.f32x2 %0, %1, %2, %3;" : "=l"(d) : "l"(a), "l"(b), "l"(c));
    return d;
}
__device__ __forceinline__ float2 unpack2(unsigned long long v) {
    float2 f;
    asm("mov.b64 {%0, %1}, %2;" : "=f"(f.x), "=f"(f.y) : "l"(v));
    return f;
}

// ---------------- cp.async helpers ----------------------------------------
__device__ __forceinline__ void cp_async16(unsigned int smem_dst, const void* gsrc) {
    asm volatile("cp.async.ca.shared.global [%0], [%1], 16;"
                 :: "r"(smem_dst), "l"(gsrc) : "memory");
}
// src-size variant: copies src_sz bytes, zero-fills the rest of 16
__device__ __forceinline__ void cp_async16z(unsigned int smem_dst, const void* gsrc, int src_sz) {
    asm volatile("cp.async.ca.shared.global [%0], [%1], 16, %2;"
                 :: "r"(smem_dst), "l"(gsrc), "r"(src_sz) : "memory");
}
__device__ __forceinline__ void cp_commit() {
    asm volatile("cp.async.commit_group;" ::: "memory");
}
__device__ __forceinline__ void cp_wait1() {
    asm volatile("cp.async.wait_group 1;" ::: "memory");
}
__device__ __forceinline__ void cp_wait0() {
    asm volatile("cp.async.wait_group 0;" ::: "memory");
}

// ---------------- zero + dtype probe (one launch) --------------------------
__global__ void zero_kernel(const int* __restrict__ ei32, int n) {
    int i = blockIdx.x * blockDim.x + threadIdx.x;
    if (i < n) g_deg[i] = 0;
    if (i < 64) { g_blk_flag[i] = 0; }
    if (blockIdx.x == 0) {
        if (threadIdx.x == 0) g_not64 = 0;
        __syncthreads();
        if (threadIdx.x < 256 && ei32[2 * threadIdx.x + 1] != 0)
            atomicOr(&g_not64, 1);
    }
}

__global__ void hist_kernel(const void* __restrict__ eiv, int E) {
    int e = blockIdx.x * blockDim.x + threadIdx.x;
    if (e >= E) return;
    int d;
    if (g_not64) d = ((const int*)eiv)[E + e];
    else         d = (int)((const long long*)eiv)[E + e];
    atomicAdd(&g_deg[d], 1);
}

// ---- single-pass decoupled-lookback exclusive scan ------------------------
__global__ void scan_lookback_kernel(int n, int nb) {
    const int b = blockIdx.x;
    const int t = threadIdx.x;
    const int lane = t & 31, wid = t >> 5;
    int i0 = b * 1024 + t * 4;

    int vals[4]; int local = 0;
#pragma unroll
    for (int u = 0; u < 4; u++) {
        int i = i0 + u;
        vals[u] = (i < n) ? g_deg[i] : 0;
        local += vals[u];
    }
    int incl = local;
#pragma unroll
    for (int off = 1; off < 32; off <<= 1) {
        int u = __shfl_up_sync(0xffffffffu, incl, off);
        if (lane >= off) incl += u;
    }
    __shared__ int ws[8], wexcl[8];
    __shared__ int s_prefix;
    if (lane == 31) ws[wid] = incl;
    __syncthreads();
    if (t < 8) {
        int s = ws[t];
        int si = s;
#pragma unroll
        for (int off = 1; off < 8; off <<= 1) {
            int u = __shfl_up_sync(0xffu, si, off);
            if (t >= off) si += u;
        }
        wexcl[t] = si - s;
    }
    __syncthreads();
    const int total = wexcl[7] + ws[7];

    if (t == 0) {
        g_blk_agg[b] = total;
        __threadfence();
        ((volatile int*)g_blk_flag)[b] = 1;
    }

    if (wid == 0) {
        int prefix = 0;
        int j = b - 1;
        while (j >= 0) {
            int jj = j - lane;
            int f = 0, v = 0;
            if (jj >= 0) {
                do { f = ((volatile int*)g_blk_flag)[jj]; } while (f == 0);
                __threadfence();
                v = (f == 2) ? ((volatile int*)g_blk_incl)[jj]
                             : ((volatile int*)g_blk_agg)[jj];
            }
            unsigned done = __ballot_sync(0xffffffffu, jj >= 0 && f == 2);
            if (done) {
                int fl = __ffs(done) - 1;
                int contrib = (lane <= fl) ? v : 0;
#pragma unroll
                for (int off = 16; off; off >>= 1)
                    contrib += __shfl_xor_sync(0xffffffffu, contrib, off);
                prefix += contrib;
                break;
            } else {
                int contrib = (jj >= 0) ? v : 0;
#pragma unroll
                for (int off = 16; off; off >>= 1)
                    contrib += __shfl_xor_sync(0xffffffffu, contrib, off);
                prefix += contrib;
                j -= 32;
            }
        }
        if (lane == 0) {
            g_blk_incl[b] = prefix + total;
            __threadfence();
            ((volatile int*)g_blk_flag)[b] = 2;
            s_prefix = prefix;
            if (b == nb - 1) g_rowptr[n] = prefix + total;
        }
    }
    __syncthreads();

    int excl = s_prefix + wexcl[wid] + (incl - local);
#pragma unroll
    for (int u = 0; u < 4; u++) {
        int i = i0 + u;
        if (i < n) { g_rowptr[i] = excl; g_fill[i] = excl; }
        excl += vals[u];
    }
}

__global__ void scatter_kernel(const void* __restrict__ eiv, int E) {
    int e = blockIdx.x * blockDim.x + threadIdx.x;
    if (e >= E) return;
    int s, d;
    if (g_not64) {
        s = ((const int*)eiv)[e];
        d = ((const int*)eiv)[E + e];
    } else {
        s = (int)((const long long*)eiv)[e];
        d = (int)((const long long*)eiv)[E + e];
    }
    int pos = atomicAdd(&g_fill[d], 1);
    g_col[pos] = s;
}

// ---------------- mean aggregation: one warp per dst node, 4x unrolled ----
__global__ void aggregate_kernel(const float4* __restrict__ x, int n, int use_h1) {
    int warp = (blockIdx.x * blockDim.x + threadIdx.x) >> 5;
    int lane = threadIdx.x & 31;
    if (warp >= n) return;
    const float4* __restrict__ src = use_h1 ? (const float4*)g_h1 : x;
    int beg = g_rowptr[warp];
    int end = g_rowptr[warp + 1];
    float4 acc = make_float4(0.f, 0.f, 0.f, 0.f);
    int e = beg;
    for (; e + 4 <= end; e += 4) {
        int s0 = g_col[e], s1 = g_col[e + 1], s2 = g_col[e + 2], s3 = g_col[e + 3];
        float4 v0 = src[(long)s0 * 32 + lane];
        float4 v1 = src[(long)s1 * 32 + lane];
        float4 v2 = src[(long)s2 * 32 + lane];
        float4 v3 = src[(long)s3 * 32 + lane];
        acc.x += v0.x; acc.y += v0.y; acc.z += v0.z; acc.w += v0.w;
        acc.x += v1.x; acc.y += v1.y; acc.z += v1.z; acc.w += v1.w;
        acc.x += v2.x; acc.y += v2.y; acc.z += v2.z; acc.w += v2.w;
        acc.x += v3.x; acc.y += v3.y; acc.z += v3.z; acc.w += v3.w;
    }
    for (; e < end; ++e) {
        int s = g_col[e];
        float4 v = src[(long)s * 32 + lane];
        acc.x += v.x; acc.y += v.y; acc.z += v.z; acc.w += v.w;
    }
    int deg = end - beg;
    float sc = 1.0f / (float)(deg > 0 ? deg : 1);
    acc.x *= sc; acc.y *= sc; acc.z *= sc; acc.w *= sc;
    ((float4*)g_agg)[(long)warp * 32 + lane] = acc;
}

// ---------------- fused SAGE linear: out = relu(agg@Wl + bl + B@Wr) -------
// Two-pass (Wl then Wr) into ONE acc bank; cp.async double-buffered stages;
// 2 CTAs/SM by construction (128-reg cap, 32 KB smem).
__global__ void __launch_bounds__(256, 2)
sage_gemm_kernel(const float* __restrict__ Bx,
                 const float* __restrict__ Wl, const float* __restrict__ bl,
                 const float* __restrict__ Wr,
                 int n, int in_sel, int out_sel) {
    __shared__ __align__(16) float sW[2][KT][128];   // [buf][k][col]
    __shared__ __align__(16) float sX[2][128][KT];   // [buf][row][k]

    const int tid = threadIdx.x;
    const int row0 = blockIdx.x * 128;

    const float* __restrict__ A  = g_agg;
    const float* __restrict__ B  = in_sel ? (const float*)g_h1 : Bx;
    float* __restrict__ out      = (out_sel == 1) ? (float*)g_h1 : (float*)g_h2;

    const int tx = tid & 15;
    const int ty = tid >> 4;
    const int tc = tx * 8;
    const int tr = ty * 8;

    unsigned long long acc[8][4];
#pragma unroll
    for (int i = 0; i < 8; i++)
#pragma unroll
        for (int j = 0; j < 4; j++) acc[i][j] = 0ull;

    const unsigned int sW_base = (unsigned int)__cvta_generic_to_shared(&sW[0][0][0]);
    const unsigned int sX_base = (unsigned int)__cvta_generic_to_shared(&sX[0][0][0]);

    // per-thread load slots
    const int wk0 = tid >> 5,        wc0 = (tid & 31) * 4;          // weight f4 slot 0
    const int wk1 = (tid + 256) >> 5, wc1 = wc0;                    // slot 1 (kk+8)
    const int xr0 = tid >> 2,        xc0 = (tid & 3) * 4;           // X slots
    const int xr1 = (tid + 256) >> 2, xc1 = xc0;

    // stage s: 0..15; mat = s>>3 (0: A/Wl, 1: B/Wr), kofs = (s&7)*KT
    #define LOAD_STAGE(s, buf)                                                  \
    do {                                                                        \
        int _mat = (s) >> 3;                                                    \
        int _kofs = ((s) & 7) * KT;                                             \
        const float* _W = _mat ? Wr : Wl;                                       \
        const float* _X = _mat ? B : A;                                         \
        cp_async16(sW_base + (((buf) * KT + wk0) * 128 + wc0) * 4,              \
                   _W + (_kofs + wk0) * 128 + wc0);                             \
        cp_async16(sW_base + (((buf) * KT + wk1) * 128 + wc1) * 4,              \
                   _W + (_kofs + wk1) * 128 + wc1);                             \
        int _g0 = row0 + xr0, _g1 = row0 + xr1;                                 \
        int _c0 = (_g0 < n) ? _g0 : 0, _c1 = (_g1 < n) ? _g1 : 0;               \
        cp_async16z(sX_base + (((buf) * 128 + xr0) * KT + xc0) * 4,             \
                    _X + (long)_c0 * 128 + _kofs + xc0, (_g0 < n) ? 16 : 0);    \
        cp_async16z(sX_base + (((buf) * 128 + xr1) * KT + xc1) * 4,             \
                    _X + (long)_c1 * 128 + _kofs + xc1, (_g1 < n) ? 16 : 0);    \
        cp_commit();                                                            \
    } while (0)

    LOAD_STAGE(0, 0);

    for (int s = 0; s < 16; s++) {
        const int buf = s & 1;
        if (s < 15) {
            LOAD_STAGE(s + 1, buf ^ 1);
            cp_wait1();
        } else {
            cp_wait0();
        }
        __syncthreads();

#pragma unroll
        for (int kk = 0; kk < KT; kk++) {
            ulonglong2 w01 = *(const ulonglong2*)&sW[buf][kk][tc];
            ulonglong2 w23 = *(const ulonglong2*)&sW[buf][kk][tc + 4];
            unsigned long long wv[4] = {w01.x, w01.y, w23.x, w23.y};
            float xv[8];
#pragma unroll
            for (int i = 0; i < 8; i++) xv[i] = sX[buf][tr + i][kk];
#pragma unroll
            for (int i = 0; i < 8; i++) {
                unsigned long long x2 = pack2(xv[i], xv[i]);
#pragma unroll
                for (int j = 0; j < 4; j++)
                    acc[i][j] = fma2(x2, wv[j], acc[i][j]);
            }
        }
        __syncthreads();
    }

    float bias[8];
#pragma unroll
    for (int j = 0; j < 8; j++) bias[j] = bl[tc + j];

#pragma unroll
    for (int i = 0; i < 8; i++) {
        int gr = row0 + tr + i;
        if (gr >= n) continue;
        float v[8];
#pragma unroll
        for (int j = 0; j < 4; j++) {
            float2 p = unpack2(acc[i][j]);
            v[2 * j]     = p.x + bias[2 * j];
            v[2 * j + 1] = p.y + bias[2 * j + 1];
        }
#pragma unroll
        for (int j = 0; j < 8; j++) v[j] = v[j] > 0.f ? v[j] : 0.f;
        float4* o = (float4*)&out[(long)gr * 128 + tc];
        o[0] = make_float4(v[0], v[1], v[2], v[3]);
        o[1] = make_float4(v[4], v[5], v[6], v[7]);
    }
}

// ---------------- output head: out[i] = g_h2[i] . Wout + bout -------------
__global__ void head_kernel(const float* __restrict__ Wout,
                            const float* __restrict__ bout,
                            float* __restrict__ out, int n) {
    int warp = (blockIdx.x * blockDim.x + threadIdx.x) >> 5;
    int lane = threadIdx.x & 31;
    if (warp >= n) return;
    float4 hv = ((const float4*)g_h2)[(long)warp * 32 + lane];
    float4 wv = ((const float4*)Wout)[lane];
    float d = hv.x * wv.x + hv.y * wv.y + hv.z * wv.z + hv.w * wv.w;
#pragma unroll
    for (int off = 16; off > 0; off >>= 1)
        d += __shfl_xor_sync(0xffffffffu, d, off);
    if (lane == 0) out[warp] = d + bout[0];
}

// ---------------- launch ---------------------------------------------------
extern "C" void kernel_launch(void* const* d_in, const int* in_sizes, int n_in,
                              void* d_out, int out_size) {
    const float* x    = (const float*)d_in[0];
    const void*  ei   = d_in[1];
    const float* W1l  = (const float*)d_in[2];
    const float* b1l  = (const float*)d_in[3];
    const float* W1r  = (const float*)d_in[4];
    const float* W2l  = (const float*)d_in[5];
    const float* b2l  = (const float*)d_in[6];
    const float* W2r  = (const float*)d_in[7];
    const float* Wout = (const float*)d_in[8];
    const float* bout = (const float*)d_in[9];
    float*       out  = (float*)d_out;

    const int n = in_sizes[0] / D;    // 50000
    const int E = in_sizes[1] / 2;    // 800000
    const int nb = (n + 1023) / 1024; // scan blocks (<= 64)

    // --- CSR build ---
    zero_kernel<<<(n + 255) / 256, 256>>>((const int*)ei, n);
    hist_kernel<<<(E + 255) / 256, 256>>>(ei, E);
    scan_lookback_kernel<<<nb, 256>>>(n, nb);
    scatter_kernel<<<(E + 255) / 256, 256>>>(ei, E);

    const int aggBlocks  = (n * 32 + 255) / 256;
    const int gemmBlocks = (n + 127) / 128;

    // --- layer 1 ---
    aggregate_kernel<<<aggBlocks, 256>>>((const float4*)x, n, 0);
    sage_gemm_kernel<<<gemmBlocks, 256>>>(x, W1l, b1l, W1r, n, 0, 1);

    // --- layer 2 ---
    aggregate_kernel<<<aggBlocks, 256>>>((const float4*)x, n, 1);
    sage_gemm_kernel<<<gemmBlocks, 256>>>(x, W2l, b2l, W2r, n, 1, 2);

    // --- head ---
    head_kernel<<<(n * 32 + 255) / 256, 256>>>(Wout, bout, out, n);
}

// round 8
// speedup vs baseline: 1.5263x; 1.2914x over previous
#include <cuda_runtime.h>
#include <cuda_bf16.h>

#define N_NODES 50000
#define N_EDGES 800000
#define D 128

// ---------------- device scratch (no runtime allocation allowed) ----------
__device__ int   g_deg[N_NODES];
__device__ int   g_rowptr[N_NODES + 1];
__device__ int   g_fill[N_NODES];
__device__ int   g_col[N_EDGES];
__device__ int   g_not64;
__device__ int   g_blk_agg[64];
__device__ int   g_blk_incl[64];
__device__ int   g_blk_flag[64];

__device__ __nv_bfloat16 g_aggb[N_NODES * D];
__device__ __nv_bfloat16 g_aggs[N_NODES * D];
__device__ __nv_bfloat16 g_xb[N_NODES * D];
__device__ __nv_bfloat16 g_xs[N_NODES * D];
__device__ float         g_h1[N_NODES * D];
__device__ __nv_bfloat16 g_h1b[N_NODES * D];
__device__ __nv_bfloat16 g_h1s[N_NODES * D];
__device__ float         g_h2[N_NODES * D];
__device__ __nv_bfloat16 g_Wb[4 * 128 * 128];   // Wt hi: [mat][n][k]
__device__ __nv_bfloat16 g_Ws[4 * 128 * 128];   // Wt lo

// ---------------- helpers ---------------------------------------------------
__device__ __forceinline__ unsigned int pkbf(float a, float b) {
    __nv_bfloat16 ha = __float2bfloat16(a), hb = __float2bfloat16(b);
    return ((unsigned int)__bfloat16_as_ushort(hb) << 16) |
           (unsigned int)__bfloat16_as_ushort(ha);
}

__device__ __forceinline__ void cp_async16(unsigned int dst, const void* src) {
    asm volatile("cp.async.ca.shared.global [%0], [%1], 16;"
                 :: "r"(dst), "l"(src) : "memory");
}
__device__ __forceinline__ void cp_async16z(unsigned int dst, const void* src, int sz) {
    asm volatile("cp.async.ca.shared.global [%0], [%1], 16, %2;"
                 :: "r"(dst), "l"(src), "r"(sz) : "memory");
}
__device__ __forceinline__ void cp_commit() {
    asm volatile("cp.async.commit_group;" ::: "memory");
}
__device__ __forceinline__ void cp_wait0() {
    asm volatile("cp.async.wait_group 0;" ::: "memory");
}

// bf16 m16n8k16 row.col mma, fp32 accumulate
__device__ __forceinline__ void mma16816(float* d, const unsigned int* a,
                                         const unsigned int* b) {
    asm volatile(
        "mma.sync.aligned.m16n8k16.row.col.f32.bf16.bf16.f32 "
        "{%0,%1,%2,%3}, {%4,%5,%6,%7}, {%8,%9}, {%0,%1,%2,%3};"
        : "+f"(d[0]), "+f"(d[1]), "+f"(d[2]), "+f"(d[3])
        : "r"(a[0]), "r"(a[1]), "r"(a[2]), "r"(a[3]), "r"(b[0]), "r"(b[1]));
}

// ---------------- zero + dtype probe ---------------------------------------
__global__ void zero_kernel(const int* __restrict__ ei32, int n) {
    int i = blockIdx.x * blockDim.x + threadIdx.x;
    if (i < n) g_deg[i] = 0;
    if (i < 64) g_blk_flag[i] = 0;
    if (blockIdx.x == 0) {
        if (threadIdx.x == 0) g_not64 = 0;
        __syncthreads();
        if (threadIdx.x < 256 && ei32[2 * threadIdx.x + 1] != 0)
            atomicOr(&g_not64, 1);
    }
}

__global__ void hist_kernel(const void* __restrict__ eiv, int E) {
    int e = blockIdx.x * blockDim.x + threadIdx.x;
    if (e >= E) return;
    int d;
    if (g_not64) d = ((const int*)eiv)[E + e];
    else         d = (int)((const long long*)eiv)[E + e];
    atomicAdd(&g_deg[d], 1);
}

__global__ void scan_lookback_kernel(int n, int nb) {
    const int b = blockIdx.x;
    const int t = threadIdx.x;
    const int lane = t & 31, wid = t >> 5;
    int i0 = b * 1024 + t * 4;

    int vals[4]; int local = 0;
#pragma unroll
    for (int u = 0; u < 4; u++) {
        int i = i0 + u;
        vals[u] = (i < n) ? g_deg[i] : 0;
        local += vals[u];
    }
    int incl = local;
#pragma unroll
    for (int off = 1; off < 32; off <<= 1) {
        int u = __shfl_up_sync(0xffffffffu, incl, off);
        if (lane >= off) incl += u;
    }
    __shared__ int ws[8], wexcl[8];
    __shared__ int s_prefix;
    if (lane == 31) ws[wid] = incl;
    __syncthreads();
    if (t < 8) {
        int s = ws[t];
        int si = s;
#pragma unroll
        for (int off = 1; off < 8; off <<= 1) {
            int u = __shfl_up_sync(0xffu, si, off);
            if (t >= off) si += u;
        }
        wexcl[t] = si - s;
    }
    __syncthreads();
    const int total = wexcl[7] + ws[7];

    if (t == 0) {
        g_blk_agg[b] = total;
        __threadfence();
        ((volatile int*)g_blk_flag)[b] = 1;
    }
    if (wid == 0) {
        int prefix = 0;
        int j = b - 1;
        while (j >= 0) {
            int jj = j - lane;
            int f = 0, v = 0;
            if (jj >= 0) {
                do { f = ((volatile int*)g_blk_flag)[jj]; } while (f == 0);
                __threadfence();
                v = (f == 2) ? ((volatile int*)g_blk_incl)[jj]
                             : ((volatile int*)g_blk_agg)[jj];
            }
            unsigned done = __ballot_sync(0xffffffffu, jj >= 0 && f == 2);
            if (done) {
                int fl = __ffs(done) - 1;
                int contrib = (lane <= fl) ? v : 0;
#pragma unroll
                for (int off = 16; off; off >>= 1)
                    contrib += __shfl_xor_sync(0xffffffffu, contrib, off);
                prefix += contrib;
                break;
            } else {
                int contrib = (jj >= 0) ? v : 0;
#pragma unroll
                for (int off = 16; off; off >>= 1)
                    contrib += __shfl_xor_sync(0xffffffffu, contrib, off);
                prefix += contrib;
                j -= 32;
            }
        }
        if (lane == 0) {
            g_blk_incl[b] = prefix + total;
            __threadfence();
            ((volatile int*)g_blk_flag)[b] = 2;
            s_prefix = prefix;
            if (b == nb - 1) g_rowptr[n] = prefix + total;
        }
    }
    __syncthreads();

    int excl = s_prefix + wexcl[wid] + (incl - local);
#pragma unroll
    for (int u = 0; u < 4; u++) {
        int i = i0 + u;
        if (i < n) { g_rowptr[i] = excl; g_fill[i] = excl; }
        excl += vals[u];
    }
}

__global__ void scatter_kernel(const void* __restrict__ eiv, int E) {
    int e = blockIdx.x * blockDim.x + threadIdx.x;
    if (e >= E) return;
    int s, d;
    if (g_not64) {
        s = ((const int*)eiv)[e];
        d = ((const int*)eiv)[E + e];
    } else {
        s = (int)((const long long*)eiv)[e];
        d = (int)((const long long*)eiv)[E + e];
    }
    int pos = atomicAdd(&g_fill[d], 1);
    g_col[pos] = s;
}

// ---------------- converters ------------------------------------------------
__global__ void convert_w_kernel(const float* __restrict__ W1l,
                                 const float* __restrict__ W1r,
                                 const float* __restrict__ W2l,
                                 const float* __restrict__ W2r) {
    int idx = blockIdx.x * blockDim.x + threadIdx.x;
    if (idx >= 4 * 16384) return;
    int m = idx >> 14;
    int i = idx & 16383;
    int nn = i >> 7, kk = i & 127;
    const float* W = (m == 0) ? W1l : (m == 1) ? W1r : (m == 2) ? W2l : W2r;
    float f = W[kk * 128 + nn];
    __nv_bfloat16 hb = __float2bfloat16(f);
    float r = f - __bfloat162float(hb);
    g_Wb[m * 16384 + nn * 128 + kk] = hb;
    g_Ws[m * 16384 + nn * 128 + kk] = __float2bfloat16(r);
}

__global__ void convert_x_kernel(const float4* __restrict__ x, int n4) {
    int i = blockIdx.x * blockDim.x + threadIdx.x;
    if (i >= n4) return;
    float4 v = x[i];
    __nv_bfloat16 b0 = __float2bfloat16(v.x), b1 = __float2bfloat16(v.y);
    __nv_bfloat16 b2 = __float2bfloat16(v.z), b3 = __float2bfloat16(v.w);
    uint2 whi, wlo;
    whi.x = ((unsigned)__bfloat16_as_ushort(b1) << 16) | __bfloat16_as_ushort(b0);
    whi.y = ((unsigned)__bfloat16_as_ushort(b3) << 16) | __bfloat16_as_ushort(b2);
    wlo.x = pkbf(v.x - __bfloat162float(b0), v.y - __bfloat162float(b1));
    wlo.y = pkbf(v.z - __bfloat162float(b2), v.w - __bfloat162float(b3));
    ((uint2*)g_xb)[i] = whi;
    ((uint2*)g_xs)[i] = wlo;
}

// ---------------- mean aggregation -> bf16 hi/lo splits --------------------
__global__ void aggregate_kernel(const float4* __restrict__ x, int n, int use_h1) {
    int warp = (blockIdx.x * blockDim.x + threadIdx.x) >> 5;
    int lane = threadIdx.x & 31;
    if (warp >= n) return;
    const float4* __restrict__ src = use_h1 ? (const float4*)g_h1 : x;
    int beg = g_rowptr[warp];
    int end = g_rowptr[warp + 1];
    float4 acc = make_float4(0.f, 0.f, 0.f, 0.f);
    int e = beg;
    for (; e + 4 <= end; e += 4) {
        int s0 = g_col[e], s1 = g_col[e + 1], s2 = g_col[e + 2], s3 = g_col[e + 3];
        float4 v0 = src[(long)s0 * 32 + lane];
        float4 v1 = src[(long)s1 * 32 + lane];
        float4 v2 = src[(long)s2 * 32 + lane];
        float4 v3 = src[(long)s3 * 32 + lane];
        acc.x += v0.x; acc.y += v0.y; acc.z += v0.z; acc.w += v0.w;
        acc.x += v1.x; acc.y += v1.y; acc.z += v1.z; acc.w += v1.w;
        acc.x += v2.x; acc.y += v2.y; acc.z += v2.z; acc.w += v2.w;
        acc.x += v3.x; acc.y += v3.y; acc.z += v3.z; acc.w += v3.w;
    }
    for (; e < end; ++e) {
        int s = g_col[e];
        float4 v = src[(long)s * 32 + lane];
        acc.x += v.x; acc.y += v.y; acc.z += v.z; acc.w += v.w;
    }
    int deg = end - beg;
    float sc = 1.0f / (float)(deg > 0 ? deg : 1);
    acc.x *= sc; acc.y *= sc; acc.z *= sc; acc.w *= sc;

    __nv_bfloat16 b0 = __float2bfloat16(acc.x), b1 = __float2bfloat16(acc.y);
    __nv_bfloat16 b2 = __float2bfloat16(acc.z), b3 = __float2bfloat16(acc.w);
    uint2 whi, wlo;
    whi.x = ((unsigned)__bfloat16_as_ushort(b1) << 16) | __bfloat16_as_ushort(b0);
    whi.y = ((unsigned)__bfloat16_as_ushort(b3) << 16) | __bfloat16_as_ushort(b2);
    wlo.x = pkbf(acc.x - __bfloat162float(b0), acc.y - __bfloat162float(b1));
    wlo.y = pkbf(acc.z - __bfloat162float(b2), acc.w - __bfloat162float(b3));
    ((uint2*)g_aggb)[(long)warp * 32 + lane] = whi;
    ((uint2*)g_aggs)[(long)warp * 32 + lane] = wlo;
}

// ---------------- mma.sync bf16-split SAGE GEMM -----------------------------
// out = relu([agg, x_or_h1] @ [Wl; Wr] + bl), bf16 hi/lo split (6 segments).
// layer=0: B=x splits, W=mats 0/1, out=h1 (+splits). layer=1: B=h1 splits,
// W=mats 2/3, out=h2.
// smem rows: 64 bf16 = 128B = 8 16B-chunks, XOR swizzle chunk^(row&7).
__global__ void __launch_bounds__(256, 2)
mma_gemm_kernel(const float* __restrict__ bl, int n, int layer) {
    __shared__ __align__(16) __nv_bfloat16 sA[128 * 64];
    __shared__ __align__(16) __nv_bfloat16 sW[128 * 64];
    __shared__ float sbias[128];

    const int tid = threadIdx.x;
    const int wid = tid >> 5, lid = tid & 31;
    const int grp = lid >> 2, tg = lid & 3;
    const int wm = (wid & 3) * 32;     // warp m offset (4 warps)
    const int wn = (wid >> 2) * 64;    // warp n offset (2 warps)
    const int row0 = blockIdx.x * 128;

    const unsigned int sA_addr = (unsigned int)__cvta_generic_to_shared(sA);
    const unsigned int sW_addr = (unsigned int)__cvta_generic_to_shared(sW);

    const __nv_bfloat16* Bb = layer ? g_h1b : g_xb;
    const __nv_bfloat16* Bs = layer ? g_h1s : g_xs;
    const __nv_bfloat16* Wlb = g_Wb + (layer ? 2 : 0) * 16384;
    const __nv_bfloat16* Wls = g_Ws + (layer ? 2 : 0) * 16384;
    const __nv_bfloat16* Wrb = g_Wb + (layer ? 3 : 1) * 16384;
    const __nv_bfloat16* Wrs = g_Ws + (layer ? 3 : 1) * 16384;

    if (tid < 128) sbias[tid] = bl[tid];

    const __nv_bfloat16* Aseq[6] = { g_aggb, g_aggs, g_aggb, Bb, Bs, Bb };
    const __nv_bfloat16* Wseq[6] = { Wlb, Wlb, Wls, Wrb, Wrb, Wrs };

    float acc[2][8][4];
#pragma unroll
    for (int mt = 0; mt < 2; mt++)
#pragma unroll
        for (int nt = 0; nt < 8; nt++)
#pragma unroll
            for (int q = 0; q < 4; q++) acc[mt][nt][q] = 0.f;

    // per-thread cp.async slots: id = tid + u*256; r = id>>3 (0..127), c = id&7
    for (int h = 0; h < 12; h++) {
        const int seg = h >> 1;
        const int k0 = (h & 1) * 64;
        const __nv_bfloat16* Ap = Aseq[seg];
        const __nv_bfloat16* Wp = Wseq[seg];

        __syncthreads();   // WAR guard: prior stage's reads done before refill
#pragma unroll
        for (int u = 0; u < 4; u++) {
            int id = tid + u * 256;
            int r = id >> 3, c = id & 7;
            int gr = row0 + r;
            unsigned int dst = sA_addr + r * 128 + ((c ^ (r & 7)) * 16);
            const void* src = Ap + (long)((gr < n) ? gr : 0) * 128 + k0 + c * 8;
            cp_async16z(dst, src, (gr < n) ? 16 : 0);
        }
#pragma unroll
        for (int u = 0; u < 4; u++) {
            int id = tid + u * 256;
            int r = id >> 3, c = id & 7;
            unsigned int dst = sW_addr + r * 128 + ((c ^ (r & 7)) * 16);
            cp_async16(dst, Wp + r * 128 + k0 + c * 8);
        }
        cp_commit();
        cp_wait0();
        __syncthreads();

        // word offset helper: row r, 32-bit word kw (0..31):
        //   byte = r*128 + ((chunk^(r&7))<<4) + (kw&3)*4, chunk = kw>>2
#define SWA(r, kw) (sA[(r) * 64] , 0)  /* placeholder unused */
#pragma unroll
        for (int ks = 0; ks < 4; ks++) {
            const int kw0 = ks * 8;
            unsigned int a[2][4], b[8][2];
#pragma unroll
            for (int mt = 0; mt < 2; mt++) {
                int rb = wm + mt * 16 + grp;
#pragma unroll
                for (int q = 0; q < 4; q++) {
                    int r = rb + ((q & 1) ? 8 : 0);
                    int kw = kw0 + ((q >> 1) ? 4 : 0) + tg;
                    unsigned int byte = (unsigned)(r * 128 +
                        (((kw >> 2) ^ (r & 7)) << 4) + (kw & 3) * 4);
                    a[mt][q] = *(const unsigned int*)((const char*)sA + byte);
                }
            }
#pragma unroll
            for (int nt = 0; nt < 8; nt++) {
                int nr = wn + nt * 8 + grp;
#pragma unroll
                for (int q = 0; q < 2; q++) {
                    int kw = kw0 + (q ? 4 : 0) + tg;
                    unsigned int byte = (unsigned)(nr * 128 +
                        (((kw >> 2) ^ (nr & 7)) << 4) + (kw & 3) * 4);
                    b[nt][q] = *(const unsigned int*)((const char*)sW + byte);
                }
            }
#pragma unroll
            for (int mt = 0; mt < 2; mt++)
#pragma unroll
                for (int nt = 0; nt < 8; nt++)
                    mma16816(acc[mt][nt], a[mt], b[nt]);
        }
    }
    __syncthreads();

    // epilogue: bias + relu; write fp32 out (+ bf16 splits for layer 0)
    float* hout = layer ? g_h2 : g_h1;
#pragma unroll
    for (int mt = 0; mt < 2; mt++) {
#pragma unroll
        for (int rr = 0; rr < 2; rr++) {
            int gr = row0 + wm + mt * 16 + grp + rr * 8;
            if (gr >= n) continue;
#pragma unroll
            for (int nt = 0; nt < 8; nt++) {
                int col = wn + nt * 8 + tg * 2;
                float v0 = acc[mt][nt][rr * 2 + 0] + sbias[col];
                float v1 = acc[mt][nt][rr * 2 + 1] + sbias[col + 1];
                v0 = v0 > 0.f ? v0 : 0.f;
                v1 = v1 > 0.f ? v1 : 0.f;
                *(float2*)&hout[(long)gr * 128 + col] = make_float2(v0, v1);
                if (!layer) {
                    __nv_bfloat16 h0 = __float2bfloat16(v0);
                    __nv_bfloat16 h1v = __float2bfloat16(v1);
                    unsigned int hi = ((unsigned)__bfloat16_as_ushort(h1v) << 16) |
                                      __bfloat16_as_ushort(h0);
                    unsigned int lo = pkbf(v0 - __bfloat162float(h0),
                                           v1 - __bfloat162float(h1v));
                    *(unsigned int*)&g_h1b[(long)gr * 128 + col] = hi;
                    *(unsigned int*)&g_h1s[(long)gr * 128 + col] = lo;
                }
            }
        }
    }
}

// ---------------- output head ----------------------------------------------
__global__ void head_kernel(const float* __restrict__ Wout,
                            const float* __restrict__ bout,
                            float* __restrict__ out, int n) {
    int warp = (blockIdx.x * blockDim.x + threadIdx.x) >> 5;
    int lane = threadIdx.x & 31;
    if (warp >= n) return;
    float4 hv = ((const float4*)g_h2)[(long)warp * 32 + lane];
    float4 wv = ((const float4*)Wout)[lane];
    float d = hv.x * wv.x + hv.y * wv.y + hv.z * wv.z + hv.w * wv.w;
#pragma unroll
    for (int off = 16; off > 0; off >>= 1)
        d += __shfl_xor_sync(0xffffffffu, d, off);
    if (lane == 0) out[warp] = d + bout[0];
}

// ---------------- launch ---------------------------------------------------
extern "C" void kernel_launch(void* const* d_in, const int* in_sizes, int n_in,
                              void* d_out, int out_size) {
    const float* x    = (const float*)d_in[0];
    const void*  ei   = d_in[1];
    const float* W1l  = (const float*)d_in[2];
    const float* b1l  = (const float*)d_in[3];
    const float* W1r  = (const float*)d_in[4];
    const float* W2l  = (const float*)d_in[5];
    const float* b2l  = (const float*)d_in[6];
    const float* W2r  = (const float*)d_in[7];
    const float* Wout = (const float*)d_in[8];
    const float* bout = (const float*)d_in[9];
    float*       out  = (float*)d_out;

    const int n = in_sizes[0] / D;    // 50000
    const int E = in_sizes[1] / 2;    // 800000
    const int nb = (n + 1023) / 1024;

    // --- CSR build ---
    zero_kernel<<<(n + 255) / 256, 256>>>((const int*)ei, n);
    hist_kernel<<<(E + 255) / 256, 256>>>(ei, E);
    scan_lookback_kernel<<<nb, 256>>>(n, nb);
    scatter_kernel<<<(E + 255) / 256, 256>>>(ei, E);

    // --- conversions ---
    convert_w_kernel<<<256, 256>>>(W1l, W1r, W2l, W2r);
    convert_x_kernel<<<(n * 32 + 255) / 256, 256>>>((const float4*)x, n * 32);

    const int aggBlocks  = (n * 32 + 255) / 256;
    const int gemmBlocks = (n + 127) / 128;

    // --- layer 1 ---
    aggregate_kernel<<<aggBlocks, 256>>>((const float4*)x, n, 0);
    mma_gemm_kernel<<<gemmBlocks, 256>>>(b1l, n, 0);

    // --- layer 2 ---
    aggregate_kernel<<<aggBlocks, 256>>>((const float4*)x, n, 1);
    mma_gemm_kernel<<<gemmBlocks, 256>>>(b2l, n, 1);

    // --- head ---
    head_kernel<<<(n * 32 + 255) / 256, 256>>>(Wout, bout, out, n);
}

// round 9
// speedup vs baseline: 1.5621x; 1.0234x over previous
#include <cuda_runtime.h>
#include <cuda_bf16.h>
#include <cuda_fp16.h>

#define N_NODES 50000
#define N_EDGES 800000
#define D 128

// ---------------- device scratch (no runtime allocation allowed) ----------
__device__ int   g_deg[N_NODES];
__device__ int   g_rowptr[N_NODES + 1];
__device__ int   g_fill[N_NODES];
__device__ int   g_col[N_EDGES];
__device__ int   g_not64;
__device__ int   g_blk_agg[64];
__device__ int   g_blk_incl[64];
__device__ int   g_blk_flag[64];

__device__ __nv_bfloat16 g_aggb[N_NODES * D];
__device__ __nv_bfloat16 g_aggs[N_NODES * D];
__device__ __nv_bfloat16 g_xb[N_NODES * D];
__device__ __nv_bfloat16 g_xs[N_NODES * D];
__device__ __half        g_xh[N_NODES * D];    // fp16 mirror for gather
__device__ __nv_bfloat16 g_h1b[N_NODES * D];
__device__ __nv_bfloat16 g_h1s[N_NODES * D];
__device__ __half        g_h1h[N_NODES * D];   // fp16 mirror of h1
__device__ float         g_h2[N_NODES * D];
__device__ __nv_bfloat16 g_Wb[4 * 128 * 128];  // Wt hi: [mat][n][k]
__device__ __nv_bfloat16 g_Ws[4 * 128 * 128];  // Wt lo

// ---------------- helpers ---------------------------------------------------
__device__ __forceinline__ unsigned int pkbf(float a, float b) {
    __nv_bfloat16 ha = __float2bfloat16(a), hb = __float2bfloat16(b);
    return ((unsigned int)__bfloat16_as_ushort(hb) << 16) |
           (unsigned int)__bfloat16_as_ushort(ha);
}

__device__ __forceinline__ void cp_async16(unsigned int dst, const void* src) {
    asm volatile("cp.async.ca.shared.global [%0], [%1], 16;"
                 :: "r"(dst), "l"(src) : "memory");
}
__device__ __forceinline__ void cp_async16z(unsigned int dst, const void* src, int sz) {
    asm volatile("cp.async.ca.shared.global [%0], [%1], 16, %2;"
                 :: "r"(dst), "l"(src), "r"(sz) : "memory");
}
__device__ __forceinline__ void cp_commit() {
    asm volatile("cp.async.commit_group;" ::: "memory");
}
__device__ __forceinline__ void cp_wait0() {
    asm volatile("cp.async.wait_group 0;" ::: "memory");
}

// bf16 m16n8k16 row.col mma, fp32 accumulate
__device__ __forceinline__ void mma16816(float* d, const unsigned int* a,
                                         const unsigned int* b) {
    asm volatile(
        "mma.sync.aligned.m16n8k16.row.col.f32.bf16.bf16.f32 "
        "{%0,%1,%2,%3}, {%4,%5,%6,%7}, {%8,%9}, {%0,%1,%2,%3};"
        : "+f"(d[0]), "+f"(d[1]), "+f"(d[2]), "+f"(d[3])
        : "r"(a[0]), "r"(a[1]), "r"(a[2]), "r"(a[3]), "r"(b[0]), "r"(b[1]));
}

// ---------------- zero + dtype probe ---------------------------------------
__global__ void zero_kernel(const int* __restrict__ ei32, int n) {
    int i = blockIdx.x * blockDim.x + threadIdx.x;
    if (i < n) g_deg[i] = 0;
    if (i < 64) g_blk_flag[i] = 0;
    if (blockIdx.x == 0) {
        if (threadIdx.x == 0) g_not64 = 0;
        __syncthreads();
        if (threadIdx.x < 256 && ei32[2 * threadIdx.x + 1] != 0)
            atomicOr(&g_not64, 1);
    }
}

__global__ void hist_kernel(const void* __restrict__ eiv, int E) {
    int e = blockIdx.x * blockDim.x + threadIdx.x;
    if (e >= E) return;
    int d;
    if (g_not64) d = ((const int*)eiv)[E + e];
    else         d = (int)((const long long*)eiv)[E + e];
    atomicAdd(&g_deg[d], 1);
}

__global__ void scan_lookback_kernel(int n, int nb) {
    const int b = blockIdx.x;
    const int t = threadIdx.x;
    const int lane = t & 31, wid = t >> 5;
    int i0 = b * 1024 + t * 4;

    int vals[4]; int local = 0;
#pragma unroll
    for (int u = 0; u < 4; u++) {
        int i = i0 + u;
        vals[u] = (i < n) ? g_deg[i] : 0;
        local += vals[u];
    }
    int incl = local;
#pragma unroll
    for (int off = 1; off < 32; off <<= 1) {
        int u = __shfl_up_sync(0xffffffffu, incl, off);
        if (lane >= off) incl += u;
    }
    __shared__ int ws[8], wexcl[8];
    __shared__ int s_prefix;
    if (lane == 31) ws[wid] = incl;
    __syncthreads();
    if (t < 8) {
        int s = ws[t];
        int si = s;
#pragma unroll
        for (int off = 1; off < 8; off <<= 1) {
            int u = __shfl_up_sync(0xffu, si, off);
            if (t >= off) si += u;
        }
        wexcl[t] = si - s;
    }
    __syncthreads();
    const int total = wexcl[7] + ws[7];

    if (t == 0) {
        g_blk_agg[b] = total;
        __threadfence();
        ((volatile int*)g_blk_flag)[b] = 1;
    }
    if (wid == 0) {
        int prefix = 0;
        int j = b - 1;
        while (j >= 0) {
            int jj = j - lane;
            int f = 0, v = 0;
            if (jj >= 0) {
                do { f = ((volatile int*)g_blk_flag)[jj]; } while (f == 0);
                __threadfence();
                v = (f == 2) ? ((volatile int*)g_blk_incl)[jj]
                             : ((volatile int*)g_blk_agg)[jj];
            }
            unsigned done = __ballot_sync(0xffffffffu, jj >= 0 && f == 2);
            if (done) {
                int fl = __ffs(done) - 1;
                int contrib = (lane <= fl) ? v : 0;
#pragma unroll
                for (int off = 16; off; off >>= 1)
                    contrib += __shfl_xor_sync(0xffffffffu, contrib, off);
                prefix += contrib;
                break;
            } else {
                int contrib = (jj >= 0) ? v : 0;
#pragma unroll
                for (int off = 16; off; off >>= 1)
                    contrib += __shfl_xor_sync(0xffffffffu, contrib, off);
                prefix += contrib;
                j -= 32;
            }
        }
        if (lane == 0) {
            g_blk_incl[b] = prefix + total;
            __threadfence();
            ((volatile int*)g_blk_flag)[b] = 2;
            s_prefix = prefix;
            if (b == nb - 1) g_rowptr[n] = prefix + total;
        }
    }
    __syncthreads();

    int excl = s_prefix + wexcl[wid] + (incl - local);
#pragma unroll
    for (int u = 0; u < 4; u++) {
        int i = i0 + u;
        if (i < n) { g_rowptr[i] = excl; g_fill[i] = excl; }
        excl += vals[u];
    }
}

__global__ void scatter_kernel(const void* __restrict__ eiv, int E) {
    int e = blockIdx.x * blockDim.x + threadIdx.x;
    if (e >= E) return;
    int s, d;
    if (g_not64) {
        s = ((const int*)eiv)[e];
        d = ((const int*)eiv)[E + e];
    } else {
        s = (int)((const long long*)eiv)[e];
        d = (int)((const long long*)eiv)[E + e];
    }
    int pos = atomicAdd(&g_fill[d], 1);
    g_col[pos] = s;
}

// ---------------- converters ------------------------------------------------
__global__ void convert_w_kernel(const float* __restrict__ W1l,
                                 const float* __restrict__ W1r,
                                 const float* __restrict__ W2l,
                                 const float* __restrict__ W2r) {
    int idx = blockIdx.x * blockDim.x + threadIdx.x;
    if (idx >= 4 * 16384) return;
    int m = idx >> 14;
    int i = idx & 16383;
    int nn = i >> 7, kk = i & 127;
    const float* W = (m == 0) ? W1l : (m == 1) ? W1r : (m == 2) ? W2l : W2r;
    float f = W[kk * 128 + nn];
    __nv_bfloat16 hb = __float2bfloat16(f);
    float r = f - __bfloat162float(hb);
    g_Wb[m * 16384 + nn * 128 + kk] = hb;
    g_Ws[m * 16384 + nn * 128 + kk] = __float2bfloat16(r);
}

// x fp32 -> bf16 hi/lo splits + fp16 mirror
__global__ void convert_x_kernel(const float4* __restrict__ x, int n4) {
    int i = blockIdx.x * blockDim.x + threadIdx.x;
    if (i >= n4) return;
    float4 v = x[i];
    __nv_bfloat16 b0 = __float2bfloat16(v.x), b1 = __float2bfloat16(v.y);
    __nv_bfloat16 b2 = __float2bfloat16(v.z), b3 = __float2bfloat16(v.w);
    uint2 whi, wlo;
    whi.x = ((unsigned)__bfloat16_as_ushort(b1) << 16) | __bfloat16_as_ushort(b0);
    whi.y = ((unsigned)__bfloat16_as_ushort(b3) << 16) | __bfloat16_as_ushort(b2);
    wlo.x = pkbf(v.x - __bfloat162float(b0), v.y - __bfloat162float(b1));
    wlo.y = pkbf(v.z - __bfloat162float(b2), v.w - __bfloat162float(b3));
    ((uint2*)g_xb)[i] = whi;
    ((uint2*)g_xs)[i] = wlo;
    __half2 h01 = __floats2half2_rn(v.x, v.y);
    __half2 h23 = __floats2half2_rn(v.z, v.w);
    ((uint2*)g_xh)[i] = make_uint2(*(unsigned int*)&h01, *(unsigned int*)&h23);
}

// ---------------- mean aggregation (fp16 gather) -> bf16 hi/lo splits ------
__global__ void aggregate_kernel(int n, int use_h1) {
    int warp = (blockIdx.x * blockDim.x + threadIdx.x) >> 5;
    int lane = threadIdx.x & 31;
    if (warp >= n) return;
    const uint2* __restrict__ src =
        use_h1 ? (const uint2*)g_h1h : (const uint2*)g_xh;
    int beg = g_rowptr[warp];
    int end = g_rowptr[warp + 1];
    float4 acc = make_float4(0.f, 0.f, 0.f, 0.f);
    int e = beg;
    for (; e + 4 <= end; e += 4) {
        int s0 = g_col[e], s1 = g_col[e + 1], s2 = g_col[e + 2], s3 = g_col[e + 3];
        uint2 v0 = src[(long)s0 * 32 + lane];
        uint2 v1 = src[(long)s1 * 32 + lane];
        uint2 v2 = src[(long)s2 * 32 + lane];
        uint2 v3 = src[(long)s3 * 32 + lane];
#pragma unroll
        for (int q = 0; q < 4; q++) {
            uint2 v = (q == 0) ? v0 : (q == 1) ? v1 : (q == 2) ? v2 : v3;
            float2 f0 = __half22float2(*(__half2*)&v.x);
            float2 f1 = __half22float2(*(__half2*)&v.y);
            acc.x += f0.x; acc.y += f0.y; acc.z += f1.x; acc.w += f1.y;
        }
    }
    for (; e < end; ++e) {
        int s = g_col[e];
        uint2 v = src[(long)s * 32 + lane];
        float2 f0 = __half22float2(*(__half2*)&v.x);
        float2 f1 = __half22float2(*(__half2*)&v.y);
        acc.x += f0.x; acc.y += f0.y; acc.z += f1.x; acc.w += f1.y;
    }
    int deg = end - beg;
    float sc = 1.0f / (float)(deg > 0 ? deg : 1);
    acc.x *= sc; acc.y *= sc; acc.z *= sc; acc.w *= sc;

    __nv_bfloat16 b0 = __float2bfloat16(acc.x), b1 = __float2bfloat16(acc.y);
    __nv_bfloat16 b2 = __float2bfloat16(acc.z), b3 = __float2bfloat16(acc.w);
    uint2 whi, wlo;
    whi.x = ((unsigned)__bfloat16_as_ushort(b1) << 16) | __bfloat16_as_ushort(b0);
    whi.y = ((unsigned)__bfloat16_as_ushort(b3) << 16) | __bfloat16_as_ushort(b2);
    wlo.x = pkbf(acc.x - __bfloat162float(b0), acc.y - __bfloat162float(b1));
    wlo.y = pkbf(acc.z - __bfloat162float(b2), acc.w - __bfloat162float(b3));
    ((uint2*)g_aggb)[(long)warp * 32 + lane] = whi;
    ((uint2*)g_aggs)[(long)warp * 32 + lane] = wlo;
}

// ---------------- mma.sync bf16-split SAGE GEMM -----------------------------
// layer=0: B=x splits, W=mats 0/1, out=h1 splits + fp16 mirror.
// layer=1: B=h1 splits, W=mats 2/3, out=g_h2 fp32.
__global__ void __launch_bounds__(256, 2)
mma_gemm_kernel(const float* __restrict__ bl, int n, int layer) {
    __shared__ __align__(16) __nv_bfloat16 sA[128 * 64];
    __shared__ __align__(16) __nv_bfloat16 sW[128 * 64];
    __shared__ float sbias[128];

    const int tid = threadIdx.x;
    const int wid = tid >> 5, lid = tid & 31;
    const int grp = lid >> 2, tg = lid & 3;
    const int wm = (wid & 3) * 32;
    const int wn = (wid >> 2) * 64;
    const int row0 = blockIdx.x * 128;

    const unsigned int sA_addr = (unsigned int)__cvta_generic_to_shared(sA);
    const unsigned int sW_addr = (unsigned int)__cvta_generic_to_shared(sW);

    const __nv_bfloat16* Bb = layer ? g_h1b : g_xb;
    const __nv_bfloat16* Bs = layer ? g_h1s : g_xs;
    const __nv_bfloat16* Wlb = g_Wb + (layer ? 2 : 0) * 16384;
    const __nv_bfloat16* Wls = g_Ws + (layer ? 2 : 0) * 16384;
    const __nv_bfloat16* Wrb = g_Wb + (layer ? 3 : 1) * 16384;
    const __nv_bfloat16* Wrs = g_Ws + (layer ? 3 : 1) * 16384;

    if (tid < 128) sbias[tid] = bl[tid];

    const __nv_bfloat16* Aseq[6] = { g_aggb, g_aggs, g_aggb, Bb, Bs, Bb };
    const __nv_bfloat16* Wseq[6] = { Wlb, Wlb, Wls, Wrb, Wrb, Wrs };

    float acc[2][8][4];
#pragma unroll
    for (int mt = 0; mt < 2; mt++)
#pragma unroll
        for (int nt = 0; nt < 8; nt++)
#pragma unroll
            for (int q = 0; q < 4; q++) acc[mt][nt][q] = 0.f;

    for (int h = 0; h < 12; h++) {
        const int seg = h >> 1;
        const int k0 = (h & 1) * 64;
        const __nv_bfloat16* Ap = Aseq[seg];
        const __nv_bfloat16* Wp = Wseq[seg];

        __syncthreads();
#pragma unroll
        for (int u = 0; u < 4; u++) {
            int id = tid + u * 256;
            int r = id >> 3, c = id & 7;
            int gr = row0 + r;
            unsigned int dst = sA_addr + r * 128 + ((c ^ (r & 7)) * 16);
            const void* src = Ap + (long)((gr < n) ? gr : 0) * 128 + k0 + c * 8;
            cp_async16z(dst, src, (gr < n) ? 16 : 0);
        }
#pragma unroll
        for (int u = 0; u < 4; u++) {
            int id = tid + u * 256;
            int r = id >> 3, c = id & 7;
            unsigned int dst = sW_addr + r * 128 + ((c ^ (r & 7)) * 16);
            cp_async16(dst, Wp + r * 128 + k0 + c * 8);
        }
        cp_commit();
        cp_wait0();
        __syncthreads();

#pragma unroll
        for (int ks = 0; ks < 4; ks++) {
            const int kw0 = ks * 8;
            unsigned int a[2][4], b[8][2];
#pragma unroll
            for (int mt = 0; mt < 2; mt++) {
                int rb = wm + mt * 16 + grp;
#pragma unroll
                for (int q = 0; q < 4; q++) {
                    int r = rb + ((q & 1) ? 8 : 0);
                    int kw = kw0 + ((q >> 1) ? 4 : 0) + tg;
                    unsigned int byte = (unsigned)(r * 128 +
                        (((kw >> 2) ^ (r & 7)) << 4) + (kw & 3) * 4);
                    a[mt][q] = *(const unsigned int*)((const char*)sA + byte);
                }
            }
#pragma unroll
            for (int nt = 0; nt < 8; nt++) {
                int nr = wn + nt * 8 + grp;
#pragma unroll
                for (int q = 0; q < 2; q++) {
                    int kw = kw0 + (q ? 4 : 0) + tg;
                    unsigned int byte = (unsigned)(nr * 128 +
                        (((kw >> 2) ^ (nr & 7)) << 4) + (kw & 3) * 4);
                    b[nt][q] = *(const unsigned int*)((const char*)sW + byte);
                }
            }
#pragma unroll
            for (int mt = 0; mt < 2; mt++)
#pragma unroll
                for (int nt = 0; nt < 8; nt++)
                    mma16816(acc[mt][nt], a[mt], b[nt]);
        }
    }
    __syncthreads();

    // epilogue: bias + relu
#pragma unroll
    for (int mt = 0; mt < 2; mt++) {
#pragma unroll
        for (int rr = 0; rr < 2; rr++) {
            int gr = row0 + wm + mt * 16 + grp + rr * 8;
            if (gr >= n) continue;
#pragma unroll
            for (int nt = 0; nt < 8; nt++) {
                int col = wn + nt * 8 + tg * 2;
                float v0 = acc[mt][nt][rr * 2 + 0] + sbias[col];
                float v1 = acc[mt][nt][rr * 2 + 1] + sbias[col + 1];
                v0 = v0 > 0.f ? v0 : 0.f;
                v1 = v1 > 0.f ? v1 : 0.f;
                if (layer) {
                    *(float2*)&g_h2[(long)gr * 128 + col] = make_float2(v0, v1);
                } else {
                    __nv_bfloat16 h0 = __float2bfloat16(v0);
                    __nv_bfloat16 h1v = __float2bfloat16(v1);
                    unsigned int hi = ((unsigned)__bfloat16_as_ushort(h1v) << 16) |
                                      __bfloat16_as_ushort(h0);
                    unsigned int lo = pkbf(v0 - __bfloat162float(h0),
                                           v1 - __bfloat162float(h1v));
                    *(unsigned int*)&g_h1b[(long)gr * 128 + col] = hi;
                    *(unsigned int*)&g_h1s[(long)gr * 128 + col] = lo;
                    __half2 hh = __floats2half2_rn(v0, v1);
                    *(unsigned int*)&g_h1h[(long)gr * 128 + col] =
                        *(unsigned int*)&hh;
                }
            }
        }
    }
}

// ---------------- output head ----------------------------------------------
__global__ void head_kernel(const float* __restrict__ Wout,
                            const float* __restrict__ bout,
                            float* __restrict__ out, int n) {
    int warp = (blockIdx.x * blockDim.x + threadIdx.x) >> 5;
    int lane = threadIdx.x & 31;
    if (warp >= n) return;
    float4 hv = ((const float4*)g_h2)[(long)warp * 32 + lane];
    float4 wv = ((const float4*)Wout)[lane];
    float d = hv.x * wv.x + hv.y * wv.y + hv.z * wv.z + hv.w * wv.w;
#pragma unroll
    for (int off = 16; off > 0; off >>= 1)
        d += __shfl_xor_sync(0xffffffffu, d, off);
    if (lane == 0) out[warp] = d + bout[0];
}

// ---------------- launch ---------------------------------------------------
extern "C" void kernel_launch(void* const* d_in, const int* in_sizes, int n_in,
                              void* d_out, int out_size) {
    const float* x    = (const float*)d_in[0];
    const void*  ei   = d_in[1];
    const float* W1l  = (const float*)d_in[2];
    const float* b1l  = (const float*)d_in[3];
    const float* W1r  = (const float*)d_in[4];
    const float* W2l  = (const float*)d_in[5];
    const float* b2l  = (const float*)d_in[6];
    const float* W2r  = (const float*)d_in[7];
    const float* Wout = (const float*)d_in[8];
    const float* bout = (const float*)d_in[9];
    float*       out  = (float*)d_out;

    const int n = in_sizes[0] / D;    // 50000
    const int E = in_sizes[1] / 2;    // 800000
    const int nb = (n + 1023) / 1024;

    // --- CSR build ---
    zero_kernel<<<(n + 255) / 256, 256>>>((const int*)ei, n);
    hist_kernel<<<(E + 255) / 256, 256>>>(ei, E);
    scan_lookback_kernel<<<nb, 256>>>(n, nb);
    scatter_kernel<<<(E + 255) / 256, 256>>>(ei, E);

    // --- conversions ---
    convert_w_kernel<<<256, 256>>>(W1l, W1r, W2l, W2r);
    convert_x_kernel<<<(n * 32 + 255) / 256, 256>>>((const float4*)x, n * 32);

    const int aggBlocks  = (n * 32 + 255) / 256;
    const int gemmBlocks = (n + 127) / 128;

    // --- layer 1 ---
    aggregate_kernel<<<aggBlocks, 256>>>(n, 0);
    mma_gemm_kernel<<<gemmBlocks, 256>>>(b1l, n, 0);

    // --- layer 2 ---
    aggregate_kernel<<<aggBlocks, 256>>>(n, 1);
    mma_gemm_kernel<<<gemmBlocks, 256>>>(b2l, n, 1);

    // --- head ---
    head_kernel<<<(n * 32 + 255) / 256, 256>>>(Wout, bout, out, n);
}